// round 14
// baseline (speedup 1.0000x reference)
#include <cuda_runtime.h>
#include <cuda_bf16.h>
#include <math.h>

#define CN 16384
#define CE 131072
#define CF 128
#define CL 9
#define CR 8
#define CDOUT 1152
#define CK 1024
#define CHID 64
#define CDA 64
#define CRCUT 5.0f
#define CEPS 1e-9f
#define FPI 3.14159265358979323846f

#define OFF_AV ((long long)CN * CDOUT)
#define OFF_M  (OFF_AV + (long long)CK * CK)
#define OFF_MI (OFF_M + CN)

// ---------------- device scratch ----------------
__device__ float g_hW[CN * CF];
__device__ float g_upd[CN * CDOUT];
__device__ float g_hlocal[CN * CDOUT];
__device__ float g_part[4][CN * CF];
__device__ int   g_counts[CN];
__device__ int   g_offsets[CN + 1];
__device__ int   g_cursor[CN];
__device__ int   g_eids[CE];
__device__ float g_m[CN];
__device__ int   g_master[CK];
__device__ int   g_rank[CN];
__device__ unsigned char g_adj[CK * CK];
__device__ unsigned char g_arec[CK * CK];
__device__ float g_hm[CK * CDOUT];
__device__ float g_posm[CK * 3];
__device__ float g_q[CK * CDA];
__device__ float g_k[CK * CDA];
__device__ float g_hWh[CK * CF];
__device__ float g_hhier[CK * CDOUT];
__device__ unsigned g_updtf[CN * CDOUT];
__device__ unsigned g_wpltf[CDOUT * CDOUT];
__device__ unsigned g_wphtf[CDOUT * CDOUT];
__device__ unsigned g_updmtf[CK * CDOUT];

// ---------------- utility ----------------
__global__ void zero_int_kernel(int* p, int n) {
    int i = blockIdx.x * blockDim.x + threadIdx.x;
    if (i < n) p[i] = 0;
}
__global__ void zero_u8_kernel(unsigned char* p, int n) {
    int i = blockIdx.x * blockDim.x + threadIdx.x;
    if (i < n) p[i] = 0;
}

__device__ __forceinline__ unsigned f2tf32(float f) {
    unsigned u;
    asm("cvt.rna.tf32.f32 %0, %1;" : "=r"(u) : "f"(f));
    return u;
}

__global__ void f2tf_kernel(const float* __restrict__ in, unsigned* __restrict__ out, int n4) {
    int i = blockIdx.x * blockDim.x + threadIdx.x;
    if (i < n4) {
        float4 v = ((const float4*)in)[i];
        uint4 u = make_uint4(f2tf32(v.x), f2tf32(v.y), f2tf32(v.z), f2tf32(v.w));
        ((uint4*)out)[i] = u;
    }
}

#define CP_ASYNC16(dst_u32, src_ptr) \
    asm volatile("cp.async.cg.shared.global [%0], [%1], 16;" :: "r"(dst_u32), "l"(src_ptr))
#define CP_COMMIT() asm volatile("cp.async.commit_group;" ::: "memory")
#define CP_WAIT1()  asm volatile("cp.async.wait_group 1;" ::: "memory")
#define CP_WAIT0()  asm volatile("cp.async.wait_group 0;" ::: "memory")

// ================= fused big GEMM =================
// 1536 blocks. group = idx/3, rem = idx%3.
//  rem 0,1 -> tf32 block t = group*2+rem (0..1023): cols 128..1151 of hlocal
//  rem 2   -> fp32 split-K block f = group (0..511): partial f&3 of cols 0..127
#define FUSED_SMEM 56832
#define KSPLIT 288   /* 1152/4 */

__global__ __launch_bounds__(256, 2) void fused_gemms(
    const float* __restrict__ Afp, const float* __restrict__ Bfp,
    float* __restrict__ Pfp,       // 4 partial buffers, each CN*CF
    const unsigned* __restrict__ Atf, const unsigned* __restrict__ Btf,
    float* __restrict__ Ctf)
{
    extern __shared__ __align__(16) char smem_raw[];
    const int tid = threadIdx.x;
    const int group = blockIdx.x / 3;
    const int rem = blockIdx.x - group * 3;

    if (rem == 2) {
        // ---------- fp32 split-K partial: A[m0:m0+128, k0:k0+288] @ B[k0:k0+288, 0:128] ----------
        typedef float AsT[8][128];
        typedef float BsT[8][128];
        AsT* As = (AsT*)smem_raw;
        BsT* Bs = (BsT*)(smem_raw + 2 * 8 * 128 * 4);
        const int f = group;
        const int m0 = (f >> 2) * 128;
        const int ks = f & 3;
        const int k0base = ks * KSPLIT;
        const float* A = Afp + k0base;                          // col offset
        const float* B = Bfp + (long long)k0base * CDOUT;       // row offset
        float* C = Pfp + (long long)ks * CN * CF;
        const int tx = tid & 15, ty = tid >> 4;
        const int lda = CDOUT, ldb = CDOUT, ldc = CF;

        float acc[8][8];
#pragma unroll
        for (int i = 0; i < 8; i++)
#pragma unroll
            for (int j = 0; j < 8; j++) acc[i][j] = 0.f;

        const int arow = tid >> 1;
        const int akc  = (tid & 1) * 4;
        const int brow = tid >> 5;
        const int bcol = (tid & 31) * 4;

        float4 av = *(const float4*)(A + (long long)(m0 + arow) * lda + akc);
        float4 bv = *(const float4*)(B + (long long)brow * ldb + bcol);
        As[0][akc + 0][arow] = av.x; As[0][akc + 1][arow] = av.y;
        As[0][akc + 2][arow] = av.z; As[0][akc + 3][arow] = av.w;
        *(float4*)&Bs[0][brow][bcol] = bv;
        __syncthreads();

        const int KT = KSPLIT >> 3;   // 36
        for (int kt = 0; kt < KT; ++kt) {
            int cur = kt & 1;
            if (kt + 1 < KT) {
                int k0 = (kt + 1) << 3;
                av = *(const float4*)(A + (long long)(m0 + arow) * lda + k0 + akc);
                bv = *(const float4*)(B + (long long)(k0 + brow) * ldb + bcol);
            }
#pragma unroll
            for (int kk = 0; kk < 8; ++kk) {
                float a[8], b[8];
                *(float4*)a       = *(const float4*)&As[cur][kk][ty * 4];
                *(float4*)(a + 4) = *(const float4*)&As[cur][kk][ty * 4 + 64];
                *(float4*)b       = *(const float4*)&Bs[cur][kk][tx * 4];
                *(float4*)(b + 4) = *(const float4*)&Bs[cur][kk][tx * 4 + 64];
#pragma unroll
                for (int i = 0; i < 8; i++)
#pragma unroll
                    for (int j = 0; j < 8; j++) acc[i][j] += a[i] * b[j];
            }
            if (kt + 1 < KT) {
                int nxt = cur ^ 1;
                As[nxt][akc + 0][arow] = av.x; As[nxt][akc + 1][arow] = av.y;
                As[nxt][akc + 2][arow] = av.z; As[nxt][akc + 3][arow] = av.w;
                *(float4*)&Bs[nxt][brow][bcol] = bv;
            }
            __syncthreads();
        }

#pragma unroll
        for (int i = 0; i < 8; i++) {
            int row = m0 + ty * 4 + (i & 3) + (i >> 2) * 64;
#pragma unroll
            for (int j = 0; j < 8; j++) {
                int col = tx * 4 + (j & 3) + (j >> 2) * 64;
                C[(long long)row * ldc + col] = acc[i][j];
            }
        }
    } else {
        // ---------- tf32 TC GEMM ----------
        typedef unsigned AsTT[128][20];
        typedef unsigned BsTT[16][136];
        AsTT* As = (AsTT*)smem_raw;
        BsTT* Bs = (BsTT*)(smem_raw + 3 * 128 * 20 * 4);
        const int t = group * 2 + rem;
        const int lane = tid & 31, wid = tid >> 5;
        const int wm = wid >> 2, wn = wid & 3;
        const int m0 = (t >> 3) * 128, n0 = (t & 7) * 128;
        const int g = lane >> 2, tq = lane & 3;
        const int lda = CDOUT, ldb = CDOUT, ldc = CDOUT;

        float acc[4][4][4];
#pragma unroll
        for (int i = 0; i < 4; i++)
#pragma unroll
            for (int j = 0; j < 4; j++)
#pragma unroll
                for (int c = 0; c < 4; c++) acc[i][j][c] = 0.f;

        const int a_r = tid >> 2, a_c = (tid & 3) * 4;
        const int b_r = tid >> 5, b_c = (tid & 31) * 4;
        const unsigned* Aptr = Atf + (long long)(m0 + a_r) * lda + a_c;
        const unsigned* Bptr = Btf + (long long)b_r * ldb + n0 + b_c;

        unsigned sA0[3], sA1[3], sB0[3], sB1[3];
#pragma unroll
        for (int s = 0; s < 3; s++) {
            sA0[s] = (unsigned)__cvta_generic_to_shared(&As[s][a_r][a_c]);
            sA1[s] = (unsigned)__cvta_generic_to_shared(&As[s][a_r + 64][a_c]);
            sB0[s] = (unsigned)__cvta_generic_to_shared(&Bs[s][b_r][b_c]);
            sB1[s] = (unsigned)__cvta_generic_to_shared(&Bs[s][b_r + 8][b_c]);
        }

        const int KT = CDOUT >> 4;
        {
            CP_ASYNC16(sA0[0], Aptr);
            CP_ASYNC16(sA1[0], Aptr + (long long)64 * lda);
            CP_ASYNC16(sB0[0], Bptr);
            CP_ASYNC16(sB1[0], Bptr + (long long)8 * ldb);
            CP_COMMIT();
            CP_ASYNC16(sA0[1], Aptr + 16);
            CP_ASYNC16(sA1[1], Aptr + 16 + (long long)64 * lda);
            CP_ASYNC16(sB0[1], Bptr + (long long)16 * ldb);
            CP_ASYNC16(sB1[1], Bptr + (long long)24 * ldb);
            CP_COMMIT();
        }

        int cur = 0;
        for (int kt = 0; kt < KT; ++kt) {
            if (kt + 1 < KT) { CP_WAIT1(); } else { CP_WAIT0(); }
            __syncthreads();
            if (kt + 2 < KT) {
                int s = cur + 2; if (s >= 3) s -= 3;
                const unsigned* Ap = Aptr + (kt + 2) * 16;
                const unsigned* Bp = Bptr + (long long)((kt + 2) * 16) * ldb;
                CP_ASYNC16(sA0[s], Ap);
                CP_ASYNC16(sA1[s], Ap + (long long)64 * lda);
                CP_ASYNC16(sB0[s], Bp);
                CP_ASYNC16(sB1[s], Bp + (long long)8 * ldb);
                CP_COMMIT();
            }
#pragma unroll
            for (int kk = 0; kk < 16; kk += 8) {
                unsigned af[4][4];
#pragma unroll
                for (int mi = 0; mi < 4; mi++) {
                    int r = wm * 64 + mi * 16 + g;
                    af[mi][0] = As[cur][r][kk + tq];
                    af[mi][1] = As[cur][r + 8][kk + tq];
                    af[mi][2] = As[cur][r][kk + tq + 4];
                    af[mi][3] = As[cur][r + 8][kk + tq + 4];
                }
                unsigned bf[4][2];
#pragma unroll
                for (int nj = 0; nj < 4; nj++) {
                    int cidx = wn * 32 + nj * 8 + g;
                    bf[nj][0] = Bs[cur][kk + tq][cidx];
                    bf[nj][1] = Bs[cur][kk + tq + 4][cidx];
                }
#pragma unroll
                for (int mi = 0; mi < 4; mi++)
#pragma unroll
                    for (int nj = 0; nj < 4; nj++)
                        asm volatile(
                            "mma.sync.aligned.m16n8k8.row.col.f32.tf32.tf32.f32 "
                            "{%0,%1,%2,%3}, {%4,%5,%6,%7}, {%8,%9}, {%0,%1,%2,%3};"
                            : "+f"(acc[mi][nj][0]), "+f"(acc[mi][nj][1]),
                              "+f"(acc[mi][nj][2]), "+f"(acc[mi][nj][3])
                            : "r"(af[mi][0]), "r"(af[mi][1]), "r"(af[mi][2]), "r"(af[mi][3]),
                              "r"(bf[nj][0]), "r"(bf[nj][1]));
            }
            cur = (cur + 1 == 3) ? 0 : cur + 1;
        }

#pragma unroll
        for (int mi = 0; mi < 4; mi++) {
            int r = wm * 64 + mi * 16 + g;
#pragma unroll
            for (int nj = 0; nj < 4; nj++) {
                int c = wn * 32 + nj * 8 + tq * 2;
                long long i0 = (long long)(m0 + r) * ldc + n0 + c;
                long long i1 = (long long)(m0 + r + 8) * ldc + n0 + c;
                *(float2*)(Ctf + i0) = make_float2(acc[mi][nj][0], acc[mi][nj][1]);
                *(float2*)(Ctf + i1) = make_float2(acc[mi][nj][2], acc[mi][nj][3]);
            }
        }
    }
}

// combine split-K partials: hlocal[:, :CF] = ((p0+p1)+(p2+p3)) + h
__global__ __launch_bounds__(128) void combine_kernel(
    const float* __restrict__ P, const float* __restrict__ h,
    float* __restrict__ hlocal)
{
    int n = blockIdx.x, tid = threadIdx.x;
    long long i = (long long)n * CF + tid;
    float s = (P[i] + P[(long long)CN * CF + i]) +
              (P[(long long)2 * CN * CF + i] + P[(long long)3 * CN * CF + i]);
    hlocal[(long long)n * CDOUT + tid] = s + h[i];
}

// ---------------- standalone tf32 GEMM (hhier) ----------------
__global__ __launch_bounds__(256) void tgemm128(
    const unsigned* __restrict__ A, int lda,
    const unsigned* __restrict__ B, int ldb,
    float* __restrict__ C, int ldc, int Ksize,
    const float* __restrict__ addsrc, int ldadd)
{
    __shared__ __align__(16) unsigned As[3][128][20];
    __shared__ __align__(16) unsigned Bs[3][16][136];
    const int tid = threadIdx.x;
    const int lane = tid & 31, wid = tid >> 5;
    const int wm = wid >> 2, wn = wid & 3;
    const int m0 = blockIdx.y * 128, n0 = blockIdx.x * 128;
    const int g = lane >> 2, tq = lane & 3;

    float acc[4][4][4];
#pragma unroll
    for (int i = 0; i < 4; i++)
#pragma unroll
        for (int j = 0; j < 4; j++)
#pragma unroll
            for (int c = 0; c < 4; c++) acc[i][j][c] = 0.f;

    const int a_r = tid >> 2, a_c = (tid & 3) * 4;
    const int b_r = tid >> 5, b_c = (tid & 31) * 4;
    const unsigned* Aptr = A + (long long)(m0 + a_r) * lda + a_c;
    const unsigned* Bptr = B + (long long)b_r * ldb + n0 + b_c;

    unsigned sA0[3], sA1[3], sB0[3], sB1[3];
#pragma unroll
    for (int s = 0; s < 3; s++) {
        sA0[s] = (unsigned)__cvta_generic_to_shared(&As[s][a_r][a_c]);
        sA1[s] = (unsigned)__cvta_generic_to_shared(&As[s][a_r + 64][a_c]);
        sB0[s] = (unsigned)__cvta_generic_to_shared(&Bs[s][b_r][b_c]);
        sB1[s] = (unsigned)__cvta_generic_to_shared(&Bs[s][b_r + 8][b_c]);
    }

    const int KT = Ksize >> 4;
    {
        CP_ASYNC16(sA0[0], Aptr);
        CP_ASYNC16(sA1[0], Aptr + (long long)64 * lda);
        CP_ASYNC16(sB0[0], Bptr);
        CP_ASYNC16(sB1[0], Bptr + (long long)8 * ldb);
        CP_COMMIT();
        CP_ASYNC16(sA0[1], Aptr + 16);
        CP_ASYNC16(sA1[1], Aptr + 16 + (long long)64 * lda);
        CP_ASYNC16(sB0[1], Bptr + (long long)16 * ldb);
        CP_ASYNC16(sB1[1], Bptr + (long long)24 * ldb);
        CP_COMMIT();
    }

    int cur = 0;
    for (int kt = 0; kt < KT; ++kt) {
        if (kt + 1 < KT) { CP_WAIT1(); } else { CP_WAIT0(); }
        __syncthreads();
        if (kt + 2 < KT) {
            int s = cur + 2; if (s >= 3) s -= 3;
            const unsigned* Ap = Aptr + (kt + 2) * 16;
            const unsigned* Bp = Bptr + (long long)((kt + 2) * 16) * ldb;
            CP_ASYNC16(sA0[s], Ap);
            CP_ASYNC16(sA1[s], Ap + (long long)64 * lda);
            CP_ASYNC16(sB0[s], Bp);
            CP_ASYNC16(sB1[s], Bp + (long long)8 * ldb);
            CP_COMMIT();
        }
#pragma unroll
        for (int kk = 0; kk < 16; kk += 8) {
            unsigned af[4][4];
#pragma unroll
            for (int mi = 0; mi < 4; mi++) {
                int r = wm * 64 + mi * 16 + g;
                af[mi][0] = As[cur][r][kk + tq];
                af[mi][1] = As[cur][r + 8][kk + tq];
                af[mi][2] = As[cur][r][kk + tq + 4];
                af[mi][3] = As[cur][r + 8][kk + tq + 4];
            }
            unsigned bf[4][2];
#pragma unroll
            for (int nj = 0; nj < 4; nj++) {
                int cidx = wn * 32 + nj * 8 + g;
                bf[nj][0] = Bs[cur][kk + tq][cidx];
                bf[nj][1] = Bs[cur][kk + tq + 4][cidx];
            }
#pragma unroll
            for (int mi = 0; mi < 4; mi++)
#pragma unroll
                for (int nj = 0; nj < 4; nj++)
                    asm volatile(
                        "mma.sync.aligned.m16n8k8.row.col.f32.tf32.tf32.f32 "
                        "{%0,%1,%2,%3}, {%4,%5,%6,%7}, {%8,%9}, {%0,%1,%2,%3};"
                        : "+f"(acc[mi][nj][0]), "+f"(acc[mi][nj][1]),
                          "+f"(acc[mi][nj][2]), "+f"(acc[mi][nj][3])
                        : "r"(af[mi][0]), "r"(af[mi][1]), "r"(af[mi][2]), "r"(af[mi][3]),
                          "r"(bf[nj][0]), "r"(bf[nj][1]));
        }
        cur = (cur + 1 == 3) ? 0 : cur + 1;
    }

#pragma unroll
    for (int mi = 0; mi < 4; mi++) {
        int r = wm * 64 + mi * 16 + g;
#pragma unroll
        for (int nj = 0; nj < 4; nj++) {
            int c = wn * 32 + nj * 8 + tq * 2;
            long long i0 = (long long)(m0 + r) * ldc + n0 + c;
            long long i1 = (long long)(m0 + r + 8) * ldc + n0 + c;
            float2 v0 = make_float2(acc[mi][nj][0], acc[mi][nj][1]);
            float2 v1 = make_float2(acc[mi][nj][2], acc[mi][nj][3]);
            if (addsrc) {
                long long a0 = (long long)(m0 + r) * ldadd + n0 + c;
                long long a1 = (long long)(m0 + r + 8) * ldadd + n0 + c;
                v0.x += addsrc[a0]; v0.y += addsrc[a0 + 1];
                v1.x += addsrc[a1]; v1.y += addsrc[a1 + 1];
            }
            *(float2*)(C + i0) = v0;
            *(float2*)(C + i1) = v1;
        }
    }
}

// ---------------- SGEMM 128x128 fp32 (hW) ----------------
__global__ __launch_bounds__(256) void sgemm128(
    const float* __restrict__ A, int lda,
    const float* __restrict__ B, int ldb,
    float* __restrict__ C, int ldc, int Ksize,
    const float* __restrict__ addsrc, int ldadd, int addcols)
{
    __shared__ float As[2][8][128];
    __shared__ float Bs[2][8][128];
    const int tid = threadIdx.x;
    const int tx = tid & 15, ty = tid >> 4;
    const int m0 = blockIdx.y * 128;
    const int n0 = blockIdx.x * 128;

    float acc[8][8];
#pragma unroll
    for (int i = 0; i < 8; i++)
#pragma unroll
        for (int j = 0; j < 8; j++) acc[i][j] = 0.f;

    const int arow = tid >> 1;
    const int akc  = (tid & 1) * 4;
    const int brow = tid >> 5;
    const int bcol = (tid & 31) * 4;

    float4 av = *(const float4*)(A + (long long)(m0 + arow) * lda + akc);
    float4 bv = *(const float4*)(B + (long long)brow * ldb + n0 + bcol);
    As[0][akc + 0][arow] = av.x; As[0][akc + 1][arow] = av.y;
    As[0][akc + 2][arow] = av.z; As[0][akc + 3][arow] = av.w;
    *(float4*)&Bs[0][brow][bcol] = bv;
    __syncthreads();

    const int KT = Ksize >> 3;
    for (int kt = 0; kt < KT; ++kt) {
        int cur = kt & 1;
        if (kt + 1 < KT) {
            int k0 = (kt + 1) << 3;
            av = *(const float4*)(A + (long long)(m0 + arow) * lda + k0 + akc);
            bv = *(const float4*)(B + (long long)(k0 + brow) * ldb + n0 + bcol);
        }
#pragma unroll
        for (int kk = 0; kk < 8; ++kk) {
            float a[8], b[8];
            *(float4*)a       = *(const float4*)&As[cur][kk][ty * 4];
            *(float4*)(a + 4) = *(const float4*)&As[cur][kk][ty * 4 + 64];
            *(float4*)b       = *(const float4*)&Bs[cur][kk][tx * 4];
            *(float4*)(b + 4) = *(const float4*)&Bs[cur][kk][tx * 4 + 64];
#pragma unroll
            for (int i = 0; i < 8; i++)
#pragma unroll
                for (int j = 0; j < 8; j++) acc[i][j] += a[i] * b[j];
        }
        if (kt + 1 < KT) {
            int nxt = cur ^ 1;
            As[nxt][akc + 0][arow] = av.x; As[nxt][akc + 1][arow] = av.y;
            As[nxt][akc + 2][arow] = av.z; As[nxt][akc + 3][arow] = av.w;
            *(float4*)&Bs[nxt][brow][bcol] = bv;
        }
        __syncthreads();
    }

#pragma unroll
    for (int i = 0; i < 8; i++) {
        int row = m0 + ty * 4 + (i & 3) + (i >> 2) * 64;
#pragma unroll
        for (int j = 0; j < 8; j++) {
            int col = n0 + tx * 4 + (j & 3) + (j >> 2) * 64;
            float v = acc[i][j];
            if (col < addcols) v += addsrc[(long long)row * ldadd + col];
            C[(long long)row * ldc + col] = v;
        }
    }
}

// ---------------- SGEMM 64x64 fp32 ----------------
__global__ __launch_bounds__(256) void sgemm64(
    const float* __restrict__ A, int lda,
    const float* __restrict__ B, int ldb,
    float* __restrict__ C, int ldc, int Ksize)
{
    __shared__ float As[16][64];
    __shared__ float Bs[16][64];
    const int tid = threadIdx.x;
    const int tx = tid & 15, ty = tid >> 4;
    const int m0 = blockIdx.y * 64, n0 = blockIdx.x * 64;
    float acc[4][4];
#pragma unroll
    for (int i = 0; i < 4; i++)
#pragma unroll
        for (int j = 0; j < 4; j++) acc[i][j] = 0.f;

    const int arow = tid >> 2, akc = (tid & 3) * 4;
    const int brow = tid >> 4, bcol = (tid & 15) * 4;
    const int KT = Ksize >> 4;
    for (int kt = 0; kt < KT; ++kt) {
        int k0 = kt << 4;
        float4 av = *(const float4*)(A + (long long)(m0 + arow) * lda + k0 + akc);
        float4 bv = *(const float4*)(B + (long long)(k0 + brow) * ldb + n0 + bcol);
        __syncthreads();
        As[akc + 0][arow] = av.x; As[akc + 1][arow] = av.y;
        As[akc + 2][arow] = av.z; As[akc + 3][arow] = av.w;
        *(float4*)&Bs[brow][bcol] = bv;
        __syncthreads();
#pragma unroll
        for (int kk = 0; kk < 16; ++kk) {
            float4 a4 = *(const float4*)&As[kk][ty * 4];
            float4 b4 = *(const float4*)&Bs[kk][tx * 4];
            float a[4] = {a4.x, a4.y, a4.z, a4.w};
            float b[4] = {b4.x, b4.y, b4.z, b4.w};
#pragma unroll
            for (int i = 0; i < 4; i++)
#pragma unroll
                for (int j = 0; j < 4; j++) acc[i][j] += a[i] * b[j];
        }
    }
#pragma unroll
    for (int i = 0; i < 4; i++) {
        int row = m0 + ty * 4 + i;
#pragma unroll
        for (int j = 0; j < 4; j++)
            C[(long long)row * ldc + n0 + tx * 4 + j] = acc[i][j];
    }
}

// ---------------- CSR build ----------------
__global__ void count_kernel(const int* __restrict__ dstArr, int* __restrict__ counts) {
    int e = blockIdx.x * blockDim.x + threadIdx.x;
    if (e < CE) atomicAdd(&counts[dstArr[e]], 1);
}
__global__ __launch_bounds__(1024) void scan_kernel(
    const int* __restrict__ counts, int* __restrict__ offsets, int* __restrict__ cursor)
{
    __shared__ int s[1024];
    int tid = threadIdx.x;
    int base = tid * 16;
    int loc[16]; int sum = 0;
#pragma unroll
    for (int i = 0; i < 16; i++) { loc[i] = sum; sum += counts[base + i]; }
    s[tid] = sum; __syncthreads();
    for (int off = 1; off < 1024; off <<= 1) {
        int x = (tid >= off) ? s[tid - off] : 0;
        __syncthreads();
        s[tid] += x;
        __syncthreads();
    }
    int excl = s[tid] - sum;
#pragma unroll
    for (int i = 0; i < 16; i++) { int o = excl + loc[i]; offsets[base + i] = o; cursor[base + i] = o; }
    if (tid == 1023) offsets[CN] = excl + sum;
}
__global__ void scatter_kernel(const int* __restrict__ dstArr, int* __restrict__ cursor,
                               int* __restrict__ eids) {
    int e = blockIdx.x * blockDim.x + threadIdx.x;
    if (e < CE) { int p = atomicAdd(&cursor[dstArr[e]], 1); eids[p] = e; }
}

// ---------------- edge accumulation (fused tf32 output) ----------------
__global__ __launch_bounds__(128) void edge_accum_kernel(
    const float* __restrict__ hW, const float* __restrict__ edge_sh,
    const float* __restrict__ edge_feats, const float* __restrict__ W_rad_l,
    const int* __restrict__ srcArr, const int* __restrict__ offsets,
    const int* __restrict__ eids, float* __restrict__ upd,
    unsigned* __restrict__ updtf)
{
    __shared__ float Wrl[CR][CF];
    __shared__ int list[1024];
    const int n = blockIdx.x;
    const int tid = threadIdx.x;
#pragma unroll
    for (int r = 0; r < CR; ++r) Wrl[r][tid] = W_rad_l[r * CF + tid];
    const int s0 = offsets[n], s1 = offsets[n + 1];
    const int deg = s1 - s0;
    const int use = (deg <= 1024) ? deg : 0;
    for (int i = tid; i < use; i += 128) list[i] = eids[s0 + i];
    __syncthreads();
    if (tid == 0 && use > 1) {
        for (int a = 1; a < use; a++) {
            int v = list[a]; int b = a - 1;
            while (b >= 0 && list[b] > v) { list[b + 1] = list[b]; b--; }
            list[b + 1] = v;
        }
    }
    __syncthreads();
    float acc[CL];
#pragma unroll
    for (int l = 0; l < CL; l++) acc[l] = 0.f;
    for (int q = 0; q < deg; ++q) {
        int e = (deg <= 1024) ? list[q] : eids[s0 + q];
        const float4* ef4 = (const float4*)(edge_feats + (long long)e * CR);
        float4 e0 = __ldg(&ef4[0]);
        float4 e1 = __ldg(&ef4[1]);
        float rs = e0.x * Wrl[0][tid] + e0.y * Wrl[1][tid] + e0.z * Wrl[2][tid] + e0.w * Wrl[3][tid]
                 + e1.x * Wrl[4][tid] + e1.y * Wrl[5][tid] + e1.z * Wrl[6][tid] + e1.w * Wrl[7][tid];
        int s = __ldg(&srcArr[e]);
        float t = __ldg(&hW[(long long)s * CF + tid]) * rs;
#pragma unroll
        for (int l = 0; l < CL; l++) acc[l] += __ldg(&edge_sh[(long long)e * CL + l]) * t;
    }
    long long obase = (long long)n * CDOUT + tid;
#pragma unroll
    for (int l = 0; l < CL; l++) {
        upd[obase + l * CF] = acc[l];
        updtf[obase + l * CF] = f2tf32(acc[l]);
    }
}

// ---------------- gating MLP ----------------
__global__ __launch_bounds__(128) void mlp_kernel(
    const float* __restrict__ hlocal,
    const float* __restrict__ W1, const float* __restrict__ b1,
    const float* __restrict__ W2, const float* __restrict__ b2,
    float* __restrict__ mout)
{
    __shared__ float W1s[CF][CHID];
    __shared__ float hs[16][CF];
    __shared__ float hid[16][CHID];
    const int tid = threadIdx.x;
    const int n0 = blockIdx.x * 16;
    for (int i = tid; i < CF * CHID; i += 128) W1s[i / CHID][i % CHID] = W1[i];
#pragma unroll
    for (int rr = 0; rr < 16; ++rr) hs[rr][tid] = hlocal[(long long)(n0 + rr) * CDOUT + tid];
    __syncthreads();
    for (int idx = tid; idx < 16 * CHID; idx += 128) {
        int rr = idx >> 6, j = idx & 63;
        float a = b1[j];
#pragma unroll 8
        for (int k2 = 0; k2 < CF; k2++) a += hs[rr][k2] * W1s[k2][j];
        hid[rr][j] = a > 0.f ? a : 0.f;
    }
    __syncthreads();
    int rr = tid >> 3, part = tid & 7;
    float sacc = 0.f;
    for (int j = part; j < CHID; j += 8) sacc += hid[rr][j] * W2[j];
    for (int o = 4; o > 0; o >>= 1) sacc += __shfl_down_sync(0xffffffffu, sacc, o, 8);
    if (part == 0) {
        float x = sacc + b2[0];
        mout[n0 + rr] = 1.f / (1.f + expf(-x));
    }
}

// ---------------- exact top-K (ballot scans) ----------------
__device__ __forceinline__ unsigned mapf(float f) {
    unsigned u = __float_as_uint(f);
    return (u & 0x80000000u) ? ~u : (u | 0x80000000u);
}
__global__ __launch_bounds__(1024) void topk_kernel(const float* __restrict__ m,
                                                    int* __restrict__ master)
{
    __shared__ unsigned hist[256];
    __shared__ unsigned sPref; __shared__ int sWant;
    __shared__ int wsum[32], woff[32];
    __shared__ int s_eqRun, s_chRun;
    const int tid = threadIdx.x;
    const int lane = tid & 31, wi = tid >> 5;
    unsigned prefix = 0; int want = CK;
    for (int shift = 24; shift >= 0; shift -= 8) {
        if (tid < 256) hist[tid] = 0u;
        __syncthreads();
        for (int i = tid; i < CN; i += 1024) {
            unsigned key = mapf(m[i]);
            if (shift == 24 || (key >> (shift + 8)) == prefix)
                atomicAdd(&hist[(key >> shift) & 255], 1u);
        }
        __syncthreads();
        if (tid == 0) {
            int w = want; int b = 255;
            for (int d = 255; d >= 0; d--) {
                if ((int)hist[d] >= w) { b = d; break; }
                w -= (int)hist[d];
            }
            sPref = (prefix << 8) | (unsigned)b; sWant = w;
        }
        __syncthreads();
        prefix = sPref; want = sWant;
        __syncthreads();
    }
    const unsigned T = prefix; const int needEq = want;
    if (tid == 0) { s_eqRun = 0; s_chRun = 0; }
    __syncthreads();
    for (int base = 0; base < CN; base += 1024) {
        int i = base + tid;
        unsigned key = mapf(m[i]);
        int isG = key > T;
        int isE = key == T;
        unsigned em = __ballot_sync(0xffffffffu, isE);
        if (lane == 0) wsum[wi] = __popc(em);
        __syncthreads();
        if (wi == 0) {
            int v = wsum[lane];
#pragma unroll
            for (int o = 1; o < 32; o <<= 1) {
                int t = __shfl_up_sync(0xffffffffu, v, o);
                if (lane >= o) v += t;
            }
            woff[lane] = v;
        }
        __syncthreads();
        int eqRank = s_eqRun + (wi ? woff[wi - 1] : 0) + __popc(em & ((1u << lane) - 1u));
        int chunkEq = woff[31];
        int chosen = isG || (isE && eqRank < needEq);
        unsigned cm = __ballot_sync(0xffffffffu, chosen);
        if (lane == 0) wsum[wi] = __popc(cm);
        __syncthreads();
        if (wi == 0) {
            int v = wsum[lane];
#pragma unroll
            for (int o = 1; o < 32; o <<= 1) {
                int t = __shfl_up_sync(0xffffffffu, v, o);
                if (lane >= o) v += t;
            }
            woff[lane] = v;
        }
        __syncthreads();
        int pos = s_chRun + (wi ? woff[wi - 1] : 0) + __popc(cm & ((1u << lane) - 1u));
        int chunkCh = woff[31];
        if (chosen && pos < CK) master[pos] = i;
        __syncthreads();
        if (tid == 0) { s_eqRun += chunkEq; s_chRun += chunkCh; }
        __syncthreads();
    }
}

__global__ void rank_init_kernel(int* rank) {
    int i = blockIdx.x * blockDim.x + threadIdx.x;
    if (i < CN) rank[i] = CK;
}
__global__ __launch_bounds__(1024) void rank_set_kernel(const int* __restrict__ master,
                                                        int* __restrict__ rank,
                                                        float* __restrict__ outMi) {
    int i = threadIdx.x;
    int n = master[i];
    rank[n] = i;
    outMi[i] = (float)n;
}

__global__ void adj_kernel(const int* __restrict__ src, const int* __restrict__ dst,
                           const int* __restrict__ rank, unsigned char* __restrict__ adj) {
    int e = blockIdx.x * blockDim.x + threadIdx.x;
    if (e < CE) {
        int rs = rank[src[e]], rd = rank[dst[e]];
        if (rs < CK && rd < CK) adj[(long long)rs * CK + rd] = 1;
    }
}

__global__ __launch_bounds__(128) void gather_kernel(
    const float* __restrict__ hlocal, const float* __restrict__ pos,
    const int* __restrict__ master, float* __restrict__ hm, float* __restrict__ posm)
{
    int i = blockIdx.x, tid = threadIdx.x;
    int n = master[i];
#pragma unroll
    for (int l = 0; l < CL; l++)
        hm[(long long)i * CDOUT + l * CF + tid] = hlocal[(long long)n * CDOUT + l * CF + tid];
    if (tid < 3) posm[i * 3 + tid] = pos[n * 3 + tid];
}

__global__ __launch_bounds__(256) void attn_kernel(const float* __restrict__ q,
                                                   const float* __restrict__ k,
                                                   float* __restrict__ AV) {
    __shared__ float qs[CDA];
    int i = blockIdx.x, tid = threadIdx.x;
    if (tid < CDA) qs[tid] = q[(long long)i * CDA + tid];
    __syncthreads();
    for (int j = tid; j < CK; j += 256) {
        const float* kr = k + (long long)j * CDA;
        float d = 0.f;
#pragma unroll
        for (int c = 0; c < CDA; c++) d += qs[c] * kr[c];
        float a = 1.f / (1.f + expf(-d * 0.125f));
        AV[(long long)i * CK + j] = (a > 0.5f) ? a : 0.f;
    }
}

__global__ void arec_kernel(const float* __restrict__ AV, const unsigned char* __restrict__ adj,
                            unsigned char* __restrict__ arec) {
    long long idx = (long long)blockIdx.x * blockDim.x + threadIdx.x;
    if (idx >= (long long)CK * CK) return;
    int i = (int)(idx / CK), j = (int)(idx % CK);
    unsigned char v = 0;
    if (i != j) {
        if (adj[(long long)j * CK + i]) v = 1;
        else if (AV[(long long)j * CK + i] > 0.f || AV[(long long)i * CK + j] > 0.f) v = 1;
    }
    arec[idx] = v;
}

// ---------------- geometry accumulation (tf32 output) ----------------
__global__ __launch_bounds__(128) void geom_kernel(
    const float* __restrict__ posm, const float* __restrict__ hWh,
    const unsigned char* __restrict__ arec, const float* __restrict__ Wrh_g,
    unsigned* __restrict__ updmtf)
{
    __shared__ float Wrh[CR][CF];
    __shared__ float shv[16][CL];
    __shared__ float radv[16][CR];
    __shared__ int act[16];
    const int i = blockIdx.x, tid = threadIdx.x;
#pragma unroll
    for (int r = 0; r < CR; r++) Wrh[r][tid] = Wrh_g[r * CF + tid];
    const float px = posm[i * 3], py = posm[i * 3 + 1], pz = posm[i * 3 + 2];
    float acc[CL];
#pragma unroll
    for (int l = 0; l < CL; l++) acc[l] = 0.f;

    for (int j0 = 0; j0 < CK; j0 += 16) {
        __syncthreads();
        if (tid < 16) {
            int j = j0 + tid;
            int a = arec[(long long)i * CK + j];
            act[tid] = a;
            if (a) {
                float vx = posm[j * 3] - px, vy = posm[j * 3 + 1] - py, vz = posm[j * 3 + 2] - pz;
                float rr = sqrtf(vx * vx + vy * vy + vz * vz);
                float inv = 1.f / fmaxf(rr, CEPS);
                float x = vx * inv, y = vy * inv, z = vz * inv;
                shv[tid][0] = 1.f; shv[tid][1] = x; shv[tid][2] = y; shv[tid][3] = z;
                shv[tid][4] = x * y; shv[tid][5] = y * z; shv[tid][6] = 3.f * z * z - 1.f;
                shv[tid][7] = x * z; shv[tid][8] = x * x - y * y;
                float c = sqrtf(2.f / CRCUT);
                float invr = 1.f / fmaxf(rr, CEPS);
#pragma unroll
                for (int n2 = 1; n2 <= CR; n2++)
                    radv[tid][n2 - 1] = c * sinf((float)n2 * FPI * rr / CRCUT) * invr;
            }
        }
        __syncthreads();
#pragma unroll 1
        for (int jj = 0; jj < 16; jj++) {
            if (!act[jj]) continue;
            int j = j0 + jj;
            float rw = 0.f;
#pragma unroll
            for (int r = 0; r < CR; r++) rw += radv[jj][r] * Wrh[r][tid];
            float t = hWh[(long long)j * CF + tid] * rw;
#pragma unroll
            for (int l = 0; l < CL; l++) acc[l] += shv[jj][l] * t;
        }
    }
    long long ob = (long long)i * CDOUT + tid;
#pragma unroll
    for (int l = 0; l < CL; l++) updmtf[ob + l * CF] = f2tf32(acc[l]);
}

__global__ __launch_bounds__(128) void blend_kernel(
    const float* __restrict__ hlocal, const float* __restrict__ hhier,
    const float* __restrict__ m, const int* __restrict__ rank,
    float* __restrict__ out, float* __restrict__ outm)
{
    int n = blockIdx.x, tid = threadIdx.x;
    float mv = m[n]; int rk = rank[n];
    long long b = (long long)n * CDOUT + tid;
#pragma unroll
    for (int l = 0; l < CL; l++) {
        float hl = hlocal[b + l * CF];
        float he = (rk < CK) ? hhier[(long long)rk * CDOUT + l * CF + tid] : 0.f;
        out[b + l * CF] = (1.f - mv) * hl + mv * he;
    }
    if (tid == 0) outm[n] = mv;
}

// ---------------- launch ----------------
extern "C" void kernel_launch(void* const* d_in, const int* in_sizes, int n_in,
                              void* d_out, int out_size) {
    const float* h         = (const float*)d_in[0];
    const float* pos       = (const float*)d_in[1];
    const float* edge_sh   = (const float*)d_in[2];
    const float* edge_fts  = (const float*)d_in[3];
    const float* W_node_l  = (const float*)d_in[4];
    const float* W_rad_l   = (const float*)d_in[5];
    const float* W_prod_l  = (const float*)d_in[6];
    const float* ms_W1     = (const float*)d_in[7];
    const float* ms_b1     = (const float*)d_in[8];
    const float* ms_W2     = (const float*)d_in[9];
    const float* ms_b2     = (const float*)d_in[10];
    const float* vg_Wq     = (const float*)d_in[11];
    const float* vg_Wk     = (const float*)d_in[12];
    const float* W_node_h  = (const float*)d_in[13];
    const float* W_rad_h   = (const float*)d_in[14];
    const float* W_prod_h  = (const float*)d_in[15];
    const int*   eidx      = (const int*)d_in[16];
    const int* src = eidx;
    const int* dst = eidx + CE;
    float* out = (float*)d_out;

    static int smem_set = 0;
    if (!smem_set) {
        cudaFuncSetAttribute(fused_gemms, cudaFuncAttributeMaxDynamicSharedMemorySize,
                             FUSED_SMEM);
        smem_set = 1;
    }

    void *p_hW, *p_upd, *p_hlocal, *p_part, *p_counts, *p_offsets, *p_cursor, *p_eids,
         *p_m, *p_master, *p_rank, *p_adj, *p_arec, *p_hm, *p_posm, *p_q, *p_k, *p_hWh,
         *p_hhier, *p_updtf, *p_wpltf, *p_wphtf, *p_updmtf;
    cudaGetSymbolAddress(&p_hW, g_hW);
    cudaGetSymbolAddress(&p_upd, g_upd);
    cudaGetSymbolAddress(&p_hlocal, g_hlocal);
    cudaGetSymbolAddress(&p_part, g_part);
    cudaGetSymbolAddress(&p_counts, g_counts);
    cudaGetSymbolAddress(&p_offsets, g_offsets);
    cudaGetSymbolAddress(&p_cursor, g_cursor);
    cudaGetSymbolAddress(&p_eids, g_eids);
    cudaGetSymbolAddress(&p_m, g_m);
    cudaGetSymbolAddress(&p_master, g_master);
    cudaGetSymbolAddress(&p_rank, g_rank);
    cudaGetSymbolAddress(&p_adj, g_adj);
    cudaGetSymbolAddress(&p_arec, g_arec);
    cudaGetSymbolAddress(&p_hm, g_hm);
    cudaGetSymbolAddress(&p_posm, g_posm);
    cudaGetSymbolAddress(&p_q, g_q);
    cudaGetSymbolAddress(&p_k, g_k);
    cudaGetSymbolAddress(&p_hWh, g_hWh);
    cudaGetSymbolAddress(&p_hhier, g_hhier);
    cudaGetSymbolAddress(&p_updtf, g_updtf);
    cudaGetSymbolAddress(&p_wpltf, g_wpltf);
    cudaGetSymbolAddress(&p_wphtf, g_wphtf);
    cudaGetSymbolAddress(&p_updmtf, g_updmtf);

    // CSR build
    zero_int_kernel<<<CN / 256, 256>>>((int*)p_counts, CN);
    count_kernel<<<CE / 256, 256>>>(dst, (int*)p_counts);
    scan_kernel<<<1, 1024>>>((int*)p_counts, (int*)p_offsets, (int*)p_cursor);
    scatter_kernel<<<CE / 256, 256>>>(dst, (int*)p_cursor, (int*)p_eids);

    // weight tf32 pre-conversion
    f2tf_kernel<<<(CDOUT * CDOUT / 4 + 255) / 256, 256>>>(W_prod_l, (unsigned*)p_wpltf,
                                                          CDOUT * CDOUT / 4);
    f2tf_kernel<<<(CDOUT * CDOUT / 4 + 255) / 256, 256>>>(W_prod_h, (unsigned*)p_wphtf,
                                                          CDOUT * CDOUT / 4);

    // hW = h @ W_node_l (fp32)
    sgemm128<<<dim3(1, CN / 128), 256>>>(h, CF, W_node_l, CF, (float*)p_hW, CF, CF,
                                         (const float*)0, 0, 0);
    // edge message accumulation (fp32 + fused tf32 output)
    edge_accum_kernel<<<CN, 128>>>((const float*)p_hW, edge_sh, edge_fts, W_rad_l,
                                   src, (const int*)p_offsets, (const int*)p_eids,
                                   (float*)p_upd, (unsigned*)p_updtf);
    // fused: fp32 split-K=4 (cols 0..127) interleaved with tf32 TC (cols 128..1151)
    fused_gemms<<<1536, 256, FUSED_SMEM>>>(
        (const float*)p_upd, W_prod_l, (float*)p_part,
        (const unsigned*)p_updtf, (const unsigned*)p_wpltf + CF, (float*)p_hlocal + CF);
    // combine split-K partials (deterministic pairwise) + h skip
    combine_kernel<<<CN, 128>>>((const float*)p_part, h, (float*)p_hlocal);
    // gating MLP
    mlp_kernel<<<CN / 16, 128>>>((const float*)p_hlocal, ms_W1, ms_b1, ms_W2, ms_b2,
                                 (float*)p_m);
    // exact top-K, sorted ascending
    topk_kernel<<<1, 1024>>>((const float*)p_m, (int*)p_master);
    rank_init_kernel<<<CN / 256, 256>>>((int*)p_rank);
    rank_set_kernel<<<1, 1024>>>((const int*)p_master, (int*)p_rank, out + OFF_MI);
    // induced adjacency
    zero_u8_kernel<<<(CK * CK) / 256, 256>>>((unsigned char*)p_adj, CK * CK);
    adj_kernel<<<CE / 256, 256>>>(src, dst, (const int*)p_rank, (unsigned char*)p_adj);
    // gather masters
    gather_kernel<<<CK, 128>>>((const float*)p_hlocal, pos, (const int*)p_master,
                               (float*)p_hm, (float*)p_posm);
    // q / k projections (exact fp32)
    sgemm64<<<dim3(CDA / 64, CK / 64), 256>>>((const float*)p_hm, CDOUT, vg_Wq, CDA,
                                              (float*)p_q, CDA, CF);
    sgemm64<<<dim3(CDA / 64, CK / 64), 256>>>((const float*)p_hm, CDOUT, vg_Wk, CDA,
                                              (float*)p_k, CDA, CF);
    // attention -> A_virtual
    attn_kernel<<<CK, 256>>>((const float*)p_q, (const float*)p_k, out + OFF_AV);
    // A_rec mask
    arec_kernel<<<(CK * CK) / 256, 256>>>(out + OFF_AV, (const unsigned char*)p_adj,
                                          (unsigned char*)p_arec);
    // hWh = h_m @ W_node_h (fp32, 32 blocks)
    sgemm64<<<dim3(CF / 64, CK / 64), 256>>>((const float*)p_hm, CDOUT,
                                             W_node_h, CF, (float*)p_hWh, CF, CDOUT);
    // masked geometry accumulation -> upd_m (tf32 bits)
    geom_kernel<<<CK, 128>>>((const float*)p_posm, (const float*)p_hWh,
                             (const unsigned char*)p_arec, W_rad_h,
                             (unsigned*)p_updmtf);
    // h_hier = upd_m @ W_prod_h + h_m (tf32 TC)
    tgemm128<<<dim3(CDOUT / 128, CK / 128), 256>>>(
        (const unsigned*)p_updmtf, CDOUT, (const unsigned*)p_wphtf, CDOUT,
        (float*)p_hhier, CDOUT, CDOUT, (const float*)p_hm, CDOUT);
    // final blend + m output
    blend_kernel<<<CN, 128>>>((const float*)p_hlocal, (const float*)p_hhier,
                              (const float*)p_m, (const int*)p_rank,
                              out, out + OFF_M);
}

// round 15
// speedup vs baseline: 1.2035x; 1.2035x over previous
#include <cuda_runtime.h>
#include <cuda_bf16.h>
#include <math.h>

#define CN 16384
#define CE 131072
#define CF 128
#define CL 9
#define CR 8
#define CDOUT 1152
#define CK 1024
#define CHID 64
#define CDA 64
#define CRCUT 5.0f
#define CEPS 1e-9f
#define FPI 3.14159265358979323846f

#define OFF_AV ((long long)CN * CDOUT)
#define OFF_M  (OFF_AV + (long long)CK * CK)
#define OFF_MI (OFF_M + CN)

// ---------------- device scratch ----------------
__device__ float g_hW[CN * CF];
__device__ float g_upd[CN * CDOUT];
__device__ float g_hlocal[CN * CDOUT];
__device__ int   g_counts[CN];
__device__ int   g_offsets[CN + 1];
__device__ int   g_cursor[CN];
__device__ int   g_eids[CE];
__device__ float g_m[CN];
__device__ int   g_master[CK];
__device__ int   g_rank[CN];
__device__ unsigned char g_adj[CK * CK];
__device__ unsigned char g_arec[CK * CK];
__device__ float g_hm[CK * CDOUT];
__device__ float g_posm[CK * 3];
__device__ float g_q[CK * CDA];
__device__ float g_k[CK * CDA];
__device__ float g_hWh[CK * CF];
__device__ float g_hhier[CK * CDOUT];
__device__ unsigned g_updtf[CN * CDOUT];
__device__ unsigned g_wpltf[CDOUT * CDOUT];
__device__ unsigned g_wphtf[CDOUT * CDOUT];
__device__ unsigned g_updmtf[CK * CDOUT];

// ---------------- utility ----------------
__global__ void zero_int_kernel(int* p, int n) {
    int i = blockIdx.x * blockDim.x + threadIdx.x;
    if (i < n) p[i] = 0;
}
__global__ void zero_u8_kernel(unsigned char* p, int n) {
    int i = blockIdx.x * blockDim.x + threadIdx.x;
    if (i < n) p[i] = 0;
}

__device__ __forceinline__ unsigned f2tf32(float f) {
    unsigned u;
    asm("cvt.rna.tf32.f32 %0, %1;" : "=r"(u) : "f"(f));
    return u;
}

__global__ void f2tf_kernel(const float* __restrict__ in, unsigned* __restrict__ out, int n4) {
    int i = blockIdx.x * blockDim.x + threadIdx.x;
    if (i < n4) {
        float4 v = ((const float4*)in)[i];
        uint4 u = make_uint4(f2tf32(v.x), f2tf32(v.y), f2tf32(v.z), f2tf32(v.w));
        ((uint4*)out)[i] = u;
    }
}

#define CP_ASYNC16(dst_u32, src_ptr) \
    asm volatile("cp.async.cg.shared.global [%0], [%1], 16;" :: "r"(dst_u32), "l"(src_ptr))
#define CP_COMMIT() asm volatile("cp.async.commit_group;" ::: "memory")
#define CP_WAIT1()  asm volatile("cp.async.wait_group 1;" ::: "memory")
#define CP_WAIT0()  asm volatile("cp.async.wait_group 0;" ::: "memory")

// ================= fused big GEMM (R13 layout) =================
// blocks 0..127   : fp32 exact slice (hlocal cols 0..127), bit-identical
// blocks 128..1151: tf32 TC GEMM (hlocal cols 128..1151), 3-stage cp.async
#define FUSED_SMEM 56832

__global__ __launch_bounds__(256, 2) void fused_gemms(
    const float* __restrict__ Afp, const float* __restrict__ Bfp,
    float* __restrict__ Cfp, const float* __restrict__ addfp,
    const unsigned* __restrict__ Atf, const unsigned* __restrict__ Btf,
    float* __restrict__ Ctf)
{
    extern __shared__ __align__(16) char smem_raw[];
    const int tid = threadIdx.x;

    if (blockIdx.x < 128) {
        typedef float AsT[8][128];
        typedef float BsT[8][128];
        AsT* As = (AsT*)smem_raw;
        BsT* Bs = (BsT*)(smem_raw + 2 * 8 * 128 * 4);
        const int tx = tid & 15, ty = tid >> 4;
        const int m0 = blockIdx.x * 128;
        const int lda = CDOUT, ldb = CDOUT, ldc = CDOUT, ldadd = CF;
        const int Ksize = CDOUT;

        float acc[8][8];
#pragma unroll
        for (int i = 0; i < 8; i++)
#pragma unroll
            for (int j = 0; j < 8; j++) acc[i][j] = 0.f;

        const int arow = tid >> 1;
        const int akc  = (tid & 1) * 4;
        const int brow = tid >> 5;
        const int bcol = (tid & 31) * 4;

        float4 av = *(const float4*)(Afp + (long long)(m0 + arow) * lda + akc);
        float4 bv = *(const float4*)(Bfp + (long long)brow * ldb + bcol);
        As[0][akc + 0][arow] = av.x; As[0][akc + 1][arow] = av.y;
        As[0][akc + 2][arow] = av.z; As[0][akc + 3][arow] = av.w;
        *(float4*)&Bs[0][brow][bcol] = bv;
        __syncthreads();

        const int KT = Ksize >> 3;
        for (int kt = 0; kt < KT; ++kt) {
            int cur = kt & 1;
            if (kt + 1 < KT) {
                int k0 = (kt + 1) << 3;
                av = *(const float4*)(Afp + (long long)(m0 + arow) * lda + k0 + akc);
                bv = *(const float4*)(Bfp + (long long)(k0 + brow) * ldb + bcol);
            }
#pragma unroll
            for (int kk = 0; kk < 8; ++kk) {
                float a[8], b[8];
                *(float4*)a       = *(const float4*)&As[cur][kk][ty * 4];
                *(float4*)(a + 4) = *(const float4*)&As[cur][kk][ty * 4 + 64];
                *(float4*)b       = *(const float4*)&Bs[cur][kk][tx * 4];
                *(float4*)(b + 4) = *(const float4*)&Bs[cur][kk][tx * 4 + 64];
#pragma unroll
                for (int i = 0; i < 8; i++)
#pragma unroll
                    for (int j = 0; j < 8; j++) acc[i][j] += a[i] * b[j];
            }
            if (kt + 1 < KT) {
                int nxt = cur ^ 1;
                As[nxt][akc + 0][arow] = av.x; As[nxt][akc + 1][arow] = av.y;
                As[nxt][akc + 2][arow] = av.z; As[nxt][akc + 3][arow] = av.w;
                *(float4*)&Bs[nxt][brow][bcol] = bv;
            }
            __syncthreads();
        }

#pragma unroll
        for (int i = 0; i < 8; i++) {
            int row = m0 + ty * 4 + (i & 3) + (i >> 2) * 64;
#pragma unroll
            for (int j = 0; j < 8; j++) {
                int col = tx * 4 + (j & 3) + (j >> 2) * 64;
                float v = acc[i][j];
                if (col < CF) v += addfp[(long long)row * ldadd + col];
                Cfp[(long long)row * ldc + col] = v;
            }
        }
    } else {
        typedef unsigned AsTT[128][20];
        typedef unsigned BsTT[16][136];
        AsTT* As = (AsTT*)smem_raw;
        BsTT* Bs = (BsTT*)(smem_raw + 3 * 128 * 20 * 4);
        const int b = blockIdx.x - 128;
        const int lane = tid & 31, wid = tid >> 5;
        const int wm = wid >> 2, wn = wid & 3;
        const int m0 = (b >> 3) * 128, n0 = (b & 7) * 128;
        const int g = lane >> 2, tq = lane & 3;
        const int lda = CDOUT, ldb = CDOUT, ldc = CDOUT;

        float acc[4][4][4];
#pragma unroll
        for (int i = 0; i < 4; i++)
#pragma unroll
            for (int j = 0; j < 4; j++)
#pragma unroll
                for (int c = 0; c < 4; c++) acc[i][j][c] = 0.f;

        const int a_r = tid >> 2, a_c = (tid & 3) * 4;
        const int b_r = tid >> 5, b_c = (tid & 31) * 4;
        const unsigned* Aptr = Atf + (long long)(m0 + a_r) * lda + a_c;
        const unsigned* Bptr = Btf + (long long)b_r * ldb + n0 + b_c;

        unsigned sA0[3], sA1[3], sB0[3], sB1[3];
#pragma unroll
        for (int s = 0; s < 3; s++) {
            sA0[s] = (unsigned)__cvta_generic_to_shared(&As[s][a_r][a_c]);
            sA1[s] = (unsigned)__cvta_generic_to_shared(&As[s][a_r + 64][a_c]);
            sB0[s] = (unsigned)__cvta_generic_to_shared(&Bs[s][b_r][b_c]);
            sB1[s] = (unsigned)__cvta_generic_to_shared(&Bs[s][b_r + 8][b_c]);
        }

        const int KT = CDOUT >> 4;
        {
            CP_ASYNC16(sA0[0], Aptr);
            CP_ASYNC16(sA1[0], Aptr + (long long)64 * lda);
            CP_ASYNC16(sB0[0], Bptr);
            CP_ASYNC16(sB1[0], Bptr + (long long)8 * ldb);
            CP_COMMIT();
            CP_ASYNC16(sA0[1], Aptr + 16);
            CP_ASYNC16(sA1[1], Aptr + 16 + (long long)64 * lda);
            CP_ASYNC16(sB0[1], Bptr + (long long)16 * ldb);
            CP_ASYNC16(sB1[1], Bptr + (long long)24 * ldb);
            CP_COMMIT();
        }

        int cur = 0;
        for (int kt = 0; kt < KT; ++kt) {
            if (kt + 1 < KT) { CP_WAIT1(); } else { CP_WAIT0(); }
            __syncthreads();
            if (kt + 2 < KT) {
                int s = cur + 2; if (s >= 3) s -= 3;
                const unsigned* Ap = Aptr + (kt + 2) * 16;
                const unsigned* Bp = Bptr + (long long)((kt + 2) * 16) * ldb;
                CP_ASYNC16(sA0[s], Ap);
                CP_ASYNC16(sA1[s], Ap + (long long)64 * lda);
                CP_ASYNC16(sB0[s], Bp);
                CP_ASYNC16(sB1[s], Bp + (long long)8 * ldb);
                CP_COMMIT();
            }
#pragma unroll
            for (int kk = 0; kk < 16; kk += 8) {
                unsigned af[4][4];
#pragma unroll
                for (int mi = 0; mi < 4; mi++) {
                    int r = wm * 64 + mi * 16 + g;
                    af[mi][0] = As[cur][r][kk + tq];
                    af[mi][1] = As[cur][r + 8][kk + tq];
                    af[mi][2] = As[cur][r][kk + tq + 4];
                    af[mi][3] = As[cur][r + 8][kk + tq + 4];
                }
                unsigned bf[4][2];
#pragma unroll
                for (int nj = 0; nj < 4; nj++) {
                    int cidx = wn * 32 + nj * 8 + g;
                    bf[nj][0] = Bs[cur][kk + tq][cidx];
                    bf[nj][1] = Bs[cur][kk + tq + 4][cidx];
                }
#pragma unroll
                for (int mi = 0; mi < 4; mi++)
#pragma unroll
                    for (int nj = 0; nj < 4; nj++)
                        asm volatile(
                            "mma.sync.aligned.m16n8k8.row.col.f32.tf32.tf32.f32 "
                            "{%0,%1,%2,%3}, {%4,%5,%6,%7}, {%8,%9}, {%0,%1,%2,%3};"
                            : "+f"(acc[mi][nj][0]), "+f"(acc[mi][nj][1]),
                              "+f"(acc[mi][nj][2]), "+f"(acc[mi][nj][3])
                            : "r"(af[mi][0]), "r"(af[mi][1]), "r"(af[mi][2]), "r"(af[mi][3]),
                              "r"(bf[nj][0]), "r"(bf[nj][1]));
            }
            cur = (cur + 1 == 3) ? 0 : cur + 1;
        }

#pragma unroll
        for (int mi = 0; mi < 4; mi++) {
            int r = wm * 64 + mi * 16 + g;
#pragma unroll
            for (int nj = 0; nj < 4; nj++) {
                int c = wn * 32 + nj * 8 + tq * 2;
                long long i0 = (long long)(m0 + r) * ldc + n0 + c;
                long long i1 = (long long)(m0 + r + 8) * ldc + n0 + c;
                *(float2*)(Ctf + i0) = make_float2(acc[mi][nj][0], acc[mi][nj][1]);
                *(float2*)(Ctf + i1) = make_float2(acc[mi][nj][2], acc[mi][nj][3]);
            }
        }
    }
}

// ---------------- standalone tf32 GEMM (hhier) ----------------
__global__ __launch_bounds__(256) void tgemm128(
    const unsigned* __restrict__ A, int lda,
    const unsigned* __restrict__ B, int ldb,
    float* __restrict__ C, int ldc, int Ksize,
    const float* __restrict__ addsrc, int ldadd)
{
    __shared__ __align__(16) unsigned As[3][128][20];
    __shared__ __align__(16) unsigned Bs[3][16][136];
    const int tid = threadIdx.x;
    const int lane = tid & 31, wid = tid >> 5;
    const int wm = wid >> 2, wn = wid & 3;
    const int m0 = blockIdx.y * 128, n0 = blockIdx.x * 128;
    const int g = lane >> 2, tq = lane & 3;

    float acc[4][4][4];
#pragma unroll
    for (int i = 0; i < 4; i++)
#pragma unroll
        for (int j = 0; j < 4; j++)
#pragma unroll
            for (int c = 0; c < 4; c++) acc[i][j][c] = 0.f;

    const int a_r = tid >> 2, a_c = (tid & 3) * 4;
    const int b_r = tid >> 5, b_c = (tid & 31) * 4;
    const unsigned* Aptr = A + (long long)(m0 + a_r) * lda + a_c;
    const unsigned* Bptr = B + (long long)b_r * ldb + n0 + b_c;

    unsigned sA0[3], sA1[3], sB0[3], sB1[3];
#pragma unroll
    for (int s = 0; s < 3; s++) {
        sA0[s] = (unsigned)__cvta_generic_to_shared(&As[s][a_r][a_c]);
        sA1[s] = (unsigned)__cvta_generic_to_shared(&As[s][a_r + 64][a_c]);
        sB0[s] = (unsigned)__cvta_generic_to_shared(&Bs[s][b_r][b_c]);
        sB1[s] = (unsigned)__cvta_generic_to_shared(&Bs[s][b_r + 8][b_c]);
    }

    const int KT = Ksize >> 4;
    {
        CP_ASYNC16(sA0[0], Aptr);
        CP_ASYNC16(sA1[0], Aptr + (long long)64 * lda);
        CP_ASYNC16(sB0[0], Bptr);
        CP_ASYNC16(sB1[0], Bptr + (long long)8 * ldb);
        CP_COMMIT();
        CP_ASYNC16(sA0[1], Aptr + 16);
        CP_ASYNC16(sA1[1], Aptr + 16 + (long long)64 * lda);
        CP_ASYNC16(sB0[1], Bptr + (long long)16 * ldb);
        CP_ASYNC16(sB1[1], Bptr + (long long)24 * ldb);
        CP_COMMIT();
    }

    int cur = 0;
    for (int kt = 0; kt < KT; ++kt) {
        if (kt + 1 < KT) { CP_WAIT1(); } else { CP_WAIT0(); }
        __syncthreads();
        if (kt + 2 < KT) {
            int s = cur + 2; if (s >= 3) s -= 3;
            const unsigned* Ap = Aptr + (kt + 2) * 16;
            const unsigned* Bp = Bptr + (long long)((kt + 2) * 16) * ldb;
            CP_ASYNC16(sA0[s], Ap);
            CP_ASYNC16(sA1[s], Ap + (long long)64 * lda);
            CP_ASYNC16(sB0[s], Bp);
            CP_ASYNC16(sB1[s], Bp + (long long)8 * ldb);
            CP_COMMIT();
        }
#pragma unroll
        for (int kk = 0; kk < 16; kk += 8) {
            unsigned af[4][4];
#pragma unroll
            for (int mi = 0; mi < 4; mi++) {
                int r = wm * 64 + mi * 16 + g;
                af[mi][0] = As[cur][r][kk + tq];
                af[mi][1] = As[cur][r + 8][kk + tq];
                af[mi][2] = As[cur][r][kk + tq + 4];
                af[mi][3] = As[cur][r + 8][kk + tq + 4];
            }
            unsigned bf[4][2];
#pragma unroll
            for (int nj = 0; nj < 4; nj++) {
                int cidx = wn * 32 + nj * 8 + g;
                bf[nj][0] = Bs[cur][kk + tq][cidx];
                bf[nj][1] = Bs[cur][kk + tq + 4][cidx];
            }
#pragma unroll
            for (int mi = 0; mi < 4; mi++)
#pragma unroll
                for (int nj = 0; nj < 4; nj++)
                    asm volatile(
                        "mma.sync.aligned.m16n8k8.row.col.f32.tf32.tf32.f32 "
                        "{%0,%1,%2,%3}, {%4,%5,%6,%7}, {%8,%9}, {%0,%1,%2,%3};"
                        : "+f"(acc[mi][nj][0]), "+f"(acc[mi][nj][1]),
                          "+f"(acc[mi][nj][2]), "+f"(acc[mi][nj][3])
                        : "r"(af[mi][0]), "r"(af[mi][1]), "r"(af[mi][2]), "r"(af[mi][3]),
                          "r"(bf[nj][0]), "r"(bf[nj][1]));
        }
        cur = (cur + 1 == 3) ? 0 : cur + 1;
    }

#pragma unroll
    for (int mi = 0; mi < 4; mi++) {
        int r = wm * 64 + mi * 16 + g;
#pragma unroll
        for (int nj = 0; nj < 4; nj++) {
            int c = wn * 32 + nj * 8 + tq * 2;
            long long i0 = (long long)(m0 + r) * ldc + n0 + c;
            long long i1 = (long long)(m0 + r + 8) * ldc + n0 + c;
            float2 v0 = make_float2(acc[mi][nj][0], acc[mi][nj][1]);
            float2 v1 = make_float2(acc[mi][nj][2], acc[mi][nj][3]);
            if (addsrc) {
                long long a0 = (long long)(m0 + r) * ldadd + n0 + c;
                long long a1 = (long long)(m0 + r + 8) * ldadd + n0 + c;
                v0.x += addsrc[a0]; v0.y += addsrc[a0 + 1];
                v1.x += addsrc[a1]; v1.y += addsrc[a1 + 1];
            }
            *(float2*)(C + i0) = v0;
            *(float2*)(C + i1) = v1;
        }
    }
}

// ---------------- SGEMM 128x128 fp32 (hW) ----------------
__global__ __launch_bounds__(256) void sgemm128(
    const float* __restrict__ A, int lda,
    const float* __restrict__ B, int ldb,
    float* __restrict__ C, int ldc, int Ksize,
    const float* __restrict__ addsrc, int ldadd, int addcols)
{
    __shared__ float As[2][8][128];
    __shared__ float Bs[2][8][128];
    const int tid = threadIdx.x;
    const int tx = tid & 15, ty = tid >> 4;
    const int m0 = blockIdx.y * 128;
    const int n0 = blockIdx.x * 128;

    float acc[8][8];
#pragma unroll
    for (int i = 0; i < 8; i++)
#pragma unroll
        for (int j = 0; j < 8; j++) acc[i][j] = 0.f;

    const int arow = tid >> 1;
    const int akc  = (tid & 1) * 4;
    const int brow = tid >> 5;
    const int bcol = (tid & 31) * 4;

    float4 av = *(const float4*)(A + (long long)(m0 + arow) * lda + akc);
    float4 bv = *(const float4*)(B + (long long)brow * ldb + n0 + bcol);
    As[0][akc + 0][arow] = av.x; As[0][akc + 1][arow] = av.y;
    As[0][akc + 2][arow] = av.z; As[0][akc + 3][arow] = av.w;
    *(float4*)&Bs[0][brow][bcol] = bv;
    __syncthreads();

    const int KT = Ksize >> 3;
    for (int kt = 0; kt < KT; ++kt) {
        int cur = kt & 1;
        if (kt + 1 < KT) {
            int k0 = (kt + 1) << 3;
            av = *(const float4*)(A + (long long)(m0 + arow) * lda + k0 + akc);
            bv = *(const float4*)(B + (long long)(k0 + brow) * ldb + n0 + bcol);
        }
#pragma unroll
        for (int kk = 0; kk < 8; ++kk) {
            float a[8], b[8];
            *(float4*)a       = *(const float4*)&As[cur][kk][ty * 4];
            *(float4*)(a + 4) = *(const float4*)&As[cur][kk][ty * 4 + 64];
            *(float4*)b       = *(const float4*)&Bs[cur][kk][tx * 4];
            *(float4*)(b + 4) = *(const float4*)&Bs[cur][kk][tx * 4 + 64];
#pragma unroll
            for (int i = 0; i < 8; i++)
#pragma unroll
                for (int j = 0; j < 8; j++) acc[i][j] += a[i] * b[j];
        }
        if (kt + 1 < KT) {
            int nxt = cur ^ 1;
            As[nxt][akc + 0][arow] = av.x; As[nxt][akc + 1][arow] = av.y;
            As[nxt][akc + 2][arow] = av.z; As[nxt][akc + 3][arow] = av.w;
            *(float4*)&Bs[nxt][brow][bcol] = bv;
        }
        __syncthreads();
    }

#pragma unroll
    for (int i = 0; i < 8; i++) {
        int row = m0 + ty * 4 + (i & 3) + (i >> 2) * 64;
#pragma unroll
        for (int j = 0; j < 8; j++) {
            int col = n0 + tx * 4 + (j & 3) + (j >> 2) * 64;
            float v = acc[i][j];
            if (col < addcols) v += addsrc[(long long)row * ldadd + col];
            C[(long long)row * ldc + col] = v;
        }
    }
}

// ---------------- SGEMM 64x64 fp32 ----------------
__global__ __launch_bounds__(256) void sgemm64(
    const float* __restrict__ A, int lda,
    const float* __restrict__ B, int ldb,
    float* __restrict__ C, int ldc, int Ksize)
{
    __shared__ float As[16][64];
    __shared__ float Bs[16][64];
    const int tid = threadIdx.x;
    const int tx = tid & 15, ty = tid >> 4;
    const int m0 = blockIdx.y * 64, n0 = blockIdx.x * 64;
    float acc[4][4];
#pragma unroll
    for (int i = 0; i < 4; i++)
#pragma unroll
        for (int j = 0; j < 4; j++) acc[i][j] = 0.f;

    const int arow = tid >> 2, akc = (tid & 3) * 4;
    const int brow = tid >> 4, bcol = (tid & 15) * 4;
    const int KT = Ksize >> 4;
    for (int kt = 0; kt < KT; ++kt) {
        int k0 = kt << 4;
        float4 av = *(const float4*)(A + (long long)(m0 + arow) * lda + k0 + akc);
        float4 bv = *(const float4*)(B + (long long)(k0 + brow) * ldb + n0 + bcol);
        __syncthreads();
        As[akc + 0][arow] = av.x; As[akc + 1][arow] = av.y;
        As[akc + 2][arow] = av.z; As[akc + 3][arow] = av.w;
        *(float4*)&Bs[brow][bcol] = bv;
        __syncthreads();
#pragma unroll
        for (int kk = 0; kk < 16; ++kk) {
            float4 a4 = *(const float4*)&As[kk][ty * 4];
            float4 b4 = *(const float4*)&Bs[kk][tx * 4];
            float a[4] = {a4.x, a4.y, a4.z, a4.w};
            float b[4] = {b4.x, b4.y, b4.z, b4.w};
#pragma unroll
            for (int i = 0; i < 4; i++)
#pragma unroll
                for (int j = 0; j < 4; j++) acc[i][j] += a[i] * b[j];
        }
    }
#pragma unroll
    for (int i = 0; i < 4; i++) {
        int row = m0 + ty * 4 + i;
#pragma unroll
        for (int j = 0; j < 4; j++)
            C[(long long)row * ldc + n0 + tx * 4 + j] = acc[i][j];
    }
}

// ---------------- CSR build ----------------
__global__ void count_kernel(const int* __restrict__ dstArr, int* __restrict__ counts) {
    int e = blockIdx.x * blockDim.x + threadIdx.x;
    if (e < CE) atomicAdd(&counts[dstArr[e]], 1);
}
__global__ __launch_bounds__(1024) void scan_kernel(
    const int* __restrict__ counts, int* __restrict__ offsets, int* __restrict__ cursor)
{
    __shared__ int s[1024];
    int tid = threadIdx.x;
    int base = tid * 16;
    int loc[16]; int sum = 0;
#pragma unroll
    for (int i = 0; i < 16; i++) { loc[i] = sum; sum += counts[base + i]; }
    s[tid] = sum; __syncthreads();
    for (int off = 1; off < 1024; off <<= 1) {
        int x = (tid >= off) ? s[tid - off] : 0;
        __syncthreads();
        s[tid] += x;
        __syncthreads();
    }
    int excl = s[tid] - sum;
#pragma unroll
    for (int i = 0; i < 16; i++) { int o = excl + loc[i]; offsets[base + i] = o; cursor[base + i] = o; }
    if (tid == 1023) offsets[CN] = excl + sum;
}
__global__ void scatter_kernel(const int* __restrict__ dstArr, int* __restrict__ cursor,
                               int* __restrict__ eids) {
    int e = blockIdx.x * blockDim.x + threadIdx.x;
    if (e < CE) { int p = atomicAdd(&cursor[dstArr[e]], 1); eids[p] = e; }
}

// ---------------- edge accumulation (fused tf32 output) ----------------
__global__ __launch_bounds__(128) void edge_accum_kernel(
    const float* __restrict__ hW, const float* __restrict__ edge_sh,
    const float* __restrict__ edge_feats, const float* __restrict__ W_rad_l,
    const int* __restrict__ srcArr, const int* __restrict__ offsets,
    const int* __restrict__ eids, float* __restrict__ upd,
    unsigned* __restrict__ updtf)
{
    __shared__ float Wrl[CR][CF];
    __shared__ int list[1024];
    const int n = blockIdx.x;
    const int tid = threadIdx.x;
#pragma unroll
    for (int r = 0; r < CR; ++r) Wrl[r][tid] = W_rad_l[r * CF + tid];
    const int s0 = offsets[n], s1 = offsets[n + 1];
    const int deg = s1 - s0;
    const int use = (deg <= 1024) ? deg : 0;
    for (int i = tid; i < use; i += 128) list[i] = eids[s0 + i];
    __syncthreads();
    if (tid == 0 && use > 1) {
        for (int a = 1; a < use; a++) {
            int v = list[a]; int b = a - 1;
            while (b >= 0 && list[b] > v) { list[b + 1] = list[b]; b--; }
            list[b + 1] = v;
        }
    }
    __syncthreads();
    float acc[CL];
#pragma unroll
    for (int l = 0; l < CL; l++) acc[l] = 0.f;
    for (int q = 0; q < deg; ++q) {
        int e = (deg <= 1024) ? list[q] : eids[s0 + q];
        const float4* ef4 = (const float4*)(edge_feats + (long long)e * CR);
        float4 e0 = __ldg(&ef4[0]);
        float4 e1 = __ldg(&ef4[1]);
        float rs = e0.x * Wrl[0][tid] + e0.y * Wrl[1][tid] + e0.z * Wrl[2][tid] + e0.w * Wrl[3][tid]
                 + e1.x * Wrl[4][tid] + e1.y * Wrl[5][tid] + e1.z * Wrl[6][tid] + e1.w * Wrl[7][tid];
        int s = __ldg(&srcArr[e]);
        float t = __ldg(&hW[(long long)s * CF + tid]) * rs;
#pragma unroll
        for (int l = 0; l < CL; l++) acc[l] += __ldg(&edge_sh[(long long)e * CL + l]) * t;
    }
    long long obase = (long long)n * CDOUT + tid;
#pragma unroll
    for (int l = 0; l < CL; l++) {
        upd[obase + l * CF] = acc[l];
        updtf[obase + l * CF] = f2tf32(acc[l]);
    }
}

// ---------------- gating MLP ----------------
__global__ __launch_bounds__(128) void mlp_kernel(
    const float* __restrict__ hlocal,
    const float* __restrict__ W1, const float* __restrict__ b1,
    const float* __restrict__ W2, const float* __restrict__ b2,
    float* __restrict__ mout)
{
    __shared__ float W1s[CF][CHID];
    __shared__ float hs[16][CF];
    __shared__ float hid[16][CHID];
    const int tid = threadIdx.x;
    const int n0 = blockIdx.x * 16;
    for (int i = tid; i < CF * CHID; i += 128) W1s[i / CHID][i % CHID] = W1[i];
#pragma unroll
    for (int rr = 0; rr < 16; ++rr) hs[rr][tid] = hlocal[(long long)(n0 + rr) * CDOUT + tid];
    __syncthreads();
    for (int idx = tid; idx < 16 * CHID; idx += 128) {
        int rr = idx >> 6, j = idx & 63;
        float a = b1[j];
#pragma unroll 8
        for (int k2 = 0; k2 < CF; k2++) a += hs[rr][k2] * W1s[k2][j];
        hid[rr][j] = a > 0.f ? a : 0.f;
    }
    __syncthreads();
    int rr = tid >> 3, part = tid & 7;
    float sacc = 0.f;
    for (int j = part; j < CHID; j += 8) sacc += hid[rr][j] * W2[j];
    for (int o = 4; o > 0; o >>= 1) sacc += __shfl_down_sync(0xffffffffu, sacc, o, 8);
    if (part == 0) {
        float x = sacc + b2[0];
        mout[n0 + rr] = 1.f / (1.f + expf(-x));
    }
}

// ---------------- exact top-K + rank/outMi fused ----------------
__device__ __forceinline__ unsigned mapf(float f) {
    unsigned u = __float_as_uint(f);
    return (u & 0x80000000u) ? ~u : (u | 0x80000000u);
}
__global__ __launch_bounds__(1024) void topk_kernel(const float* __restrict__ m,
                                                    int* __restrict__ master,
                                                    int* __restrict__ rank,
                                                    float* __restrict__ outMi)
{
    __shared__ unsigned hist[256];
    __shared__ unsigned sPref; __shared__ int sWant;
    __shared__ int wsum[32], woff[32];
    __shared__ int s_eqRun, s_chRun;
    const int tid = threadIdx.x;
    const int lane = tid & 31, wi = tid >> 5;
    unsigned prefix = 0; int want = CK;
    for (int shift = 24; shift >= 0; shift -= 8) {
        if (tid < 256) hist[tid] = 0u;
        __syncthreads();
        for (int i = tid; i < CN; i += 1024) {
            unsigned key = mapf(m[i]);
            if (shift == 24 || (key >> (shift + 8)) == prefix)
                atomicAdd(&hist[(key >> shift) & 255], 1u);
        }
        __syncthreads();
        if (tid == 0) {
            int w = want; int b = 255;
            for (int d = 255; d >= 0; d--) {
                if ((int)hist[d] >= w) { b = d; break; }
                w -= (int)hist[d];
            }
            sPref = (prefix << 8) | (unsigned)b; sWant = w;
        }
        __syncthreads();
        prefix = sPref; want = sWant;
        __syncthreads();
    }
    const unsigned T = prefix; const int needEq = want;
    if (tid == 0) { s_eqRun = 0; s_chRun = 0; }
    __syncthreads();
    for (int base = 0; base < CN; base += 1024) {
        int i = base + tid;
        unsigned key = mapf(m[i]);
        int isG = key > T;
        int isE = key == T;
        unsigned em = __ballot_sync(0xffffffffu, isE);
        if (lane == 0) wsum[wi] = __popc(em);
        __syncthreads();
        if (wi == 0) {
            int v = wsum[lane];
#pragma unroll
            for (int o = 1; o < 32; o <<= 1) {
                int t = __shfl_up_sync(0xffffffffu, v, o);
                if (lane >= o) v += t;
            }
            woff[lane] = v;
        }
        __syncthreads();
        int eqRank = s_eqRun + (wi ? woff[wi - 1] : 0) + __popc(em & ((1u << lane) - 1u));
        int chunkEq = woff[31];
        int chosen = isG || (isE && eqRank < needEq);
        unsigned cm = __ballot_sync(0xffffffffu, chosen);
        if (lane == 0) wsum[wi] = __popc(cm);
        __syncthreads();
        if (wi == 0) {
            int v = wsum[lane];
#pragma unroll
            for (int o = 1; o < 32; o <<= 1) {
                int t = __shfl_up_sync(0xffffffffu, v, o);
                if (lane >= o) v += t;
            }
            woff[lane] = v;
        }
        __syncthreads();
        int pos = s_chRun + (wi ? woff[wi - 1] : 0) + __popc(cm & ((1u << lane) - 1u));
        int chunkCh = woff[31];
        if (chosen && pos < CK) master[pos] = i;
        __syncthreads();
        if (tid == 0) { s_eqRun += chunkEq; s_chRun += chunkCh; }
        __syncthreads();
    }
    // fused rank init + set + master-index output
    for (int i = tid; i < CN; i += 1024) rank[i] = CK;
    __syncthreads();
    if (tid < CK) {
        int n = master[tid];
        rank[n] = tid;
        outMi[tid] = (float)n;
    }
}

__global__ void adj_kernel(const int* __restrict__ src, const int* __restrict__ dst,
                           const int* __restrict__ rank, unsigned char* __restrict__ adj) {
    int e = blockIdx.x * blockDim.x + threadIdx.x;
    if (e < CE) {
        int rs = rank[src[e]], rd = rank[dst[e]];
        if (rs < CK && rd < CK) adj[(long long)rs * CK + rd] = 1;
    }
}

__global__ __launch_bounds__(128) void gather_kernel(
    const float* __restrict__ hlocal, const float* __restrict__ pos,
    const int* __restrict__ master, float* __restrict__ hm, float* __restrict__ posm)
{
    int i = blockIdx.x, tid = threadIdx.x;
    int n = master[i];
#pragma unroll
    for (int l = 0; l < CL; l++)
        hm[(long long)i * CDOUT + l * CF + tid] = hlocal[(long long)n * CDOUT + l * CF + tid];
    if (tid < 3) posm[i * 3 + tid] = pos[n * 3 + tid];
}

// ---------------- attention: 16 query rows/block, K tiled through smem ----------------
// per-element math identical to the old version (serial c=0..63 fp32 dot).
__global__ __launch_bounds__(256) void attn_kernel(const float* __restrict__ q,
                                                   const float* __restrict__ k,
                                                   float* __restrict__ AV) {
    __shared__ float qs[16][CDA + 1];
    __shared__ float ks[128][CDA + 1];
    const int i0 = blockIdx.x * 16;
    const int tid = threadIdx.x;
    for (int idx = tid; idx < 16 * CDA; idx += 256)
        qs[idx >> 6][idx & 63] = q[(long long)(i0 + (idx >> 6)) * CDA + (idx & 63)];
    const int il = tid >> 4;      // 0..15
    const int jo = tid & 15;      // 0..15
    for (int jt = 0; jt < CK; jt += 128) {
        __syncthreads();
        for (int idx = tid; idx < 128 * CDA; idx += 256) {
            int r = idx >> 6, c = idx & 63;
            ks[r][c] = k[(long long)(jt + r) * CDA + c];
        }
        __syncthreads();
#pragma unroll 1
        for (int jj = 0; jj < 8; jj++) {
            int j = jo + jj * 16;  // 0..127
            float d = 0.f;
#pragma unroll
            for (int c = 0; c < CDA; c++) d += qs[il][c] * ks[j][c];
            float a = 1.f / (1.f + expf(-d * 0.125f));
            AV[(long long)(i0 + il) * CK + jt + j] = (a > 0.5f) ? a : 0.f;
        }
    }
}

__global__ void arec_kernel(const float* __restrict__ AV, const unsigned char* __restrict__ adj,
                            unsigned char* __restrict__ arec) {
    long long idx = (long long)blockIdx.x * blockDim.x + threadIdx.x;
    if (idx >= (long long)CK * CK) return;
    int i = (int)(idx / CK), j = (int)(idx % CK);
    unsigned char v = 0;
    if (i != j) {
        if (adj[(long long)j * CK + i]) v = 1;
        else if (AV[(long long)j * CK + i] > 0.f || AV[(long long)i * CK + j] > 0.f) v = 1;
    }
    arec[idx] = v;
}

// ---------------- geometry accumulation (tf32 output) ----------------
__global__ __launch_bounds__(128) void geom_kernel(
    const float* __restrict__ posm, const float* __restrict__ hWh,
    const unsigned char* __restrict__ arec, const float* __restrict__ Wrh_g,
    unsigned* __restrict__ updmtf)
{
    __shared__ float Wrh[CR][CF];
    __shared__ float shv[16][CL];
    __shared__ float radv[16][CR];
    __shared__ int act[16];
    const int i = blockIdx.x, tid = threadIdx.x;
#pragma unroll
    for (int r = 0; r < CR; r++) Wrh[r][tid] = Wrh_g[r * CF + tid];
    const float px = posm[i * 3], py = posm[i * 3 + 1], pz = posm[i * 3 + 2];
    float acc[CL];
#pragma unroll
    for (int l = 0; l < CL; l++) acc[l] = 0.f;

    for (int j0 = 0; j0 < CK; j0 += 16) {
        __syncthreads();
        if (tid < 16) {
            int j = j0 + tid;
            int a = arec[(long long)i * CK + j];
            act[tid] = a;
            if (a) {
                float vx = posm[j * 3] - px, vy = posm[j * 3 + 1] - py, vz = posm[j * 3 + 2] - pz;
                float rr = sqrtf(vx * vx + vy * vy + vz * vz);
                float inv = 1.f / fmaxf(rr, CEPS);
                float x = vx * inv, y = vy * inv, z = vz * inv;
                shv[tid][0] = 1.f; shv[tid][1] = x; shv[tid][2] = y; shv[tid][3] = z;
                shv[tid][4] = x * y; shv[tid][5] = y * z; shv[tid][6] = 3.f * z * z - 1.f;
                shv[tid][7] = x * z; shv[tid][8] = x * x - y * y;
                float c = sqrtf(2.f / CRCUT);
                float invr = 1.f / fmaxf(rr, CEPS);
#pragma unroll
                for (int n2 = 1; n2 <= CR; n2++)
                    radv[tid][n2 - 1] = c * sinf((float)n2 * FPI * rr / CRCUT) * invr;
            }
        }
        __syncthreads();
#pragma unroll 1
        for (int jj = 0; jj < 16; jj++) {
            if (!act[jj]) continue;
            int j = j0 + jj;
            float rw = 0.f;
#pragma unroll
            for (int r = 0; r < CR; r++) rw += radv[jj][r] * Wrh[r][tid];
            float t = hWh[(long long)j * CF + tid] * rw;
#pragma unroll
            for (int l = 0; l < CL; l++) acc[l] += shv[jj][l] * t;
        }
    }
    long long ob = (long long)i * CDOUT + tid;
#pragma unroll
    for (int l = 0; l < CL; l++) updmtf[ob + l * CF] = f2tf32(acc[l]);
}

__global__ __launch_bounds__(128) void blend_kernel(
    const float* __restrict__ hlocal, const float* __restrict__ hhier,
    const float* __restrict__ m, const int* __restrict__ rank,
    float* __restrict__ out, float* __restrict__ outm)
{
    int n = blockIdx.x, tid = threadIdx.x;
    float mv = m[n]; int rk = rank[n];
    long long b = (long long)n * CDOUT + tid;
#pragma unroll
    for (int l = 0; l < CL; l++) {
        float hl = hlocal[b + l * CF];
        float he = (rk < CK) ? hhier[(long long)rk * CDOUT + l * CF + tid] : 0.f;
        out[b + l * CF] = (1.f - mv) * hl + mv * he;
    }
    if (tid == 0) outm[n] = mv;
}

// ---------------- launch ----------------
extern "C" void kernel_launch(void* const* d_in, const int* in_sizes, int n_in,
                              void* d_out, int out_size) {
    const float* h         = (const float*)d_in[0];
    const float* pos       = (const float*)d_in[1];
    const float* edge_sh   = (const float*)d_in[2];
    const float* edge_fts  = (const float*)d_in[3];
    const float* W_node_l  = (const float*)d_in[4];
    const float* W_rad_l   = (const float*)d_in[5];
    const float* W_prod_l  = (const float*)d_in[6];
    const float* ms_W1     = (const float*)d_in[7];
    const float* ms_b1     = (const float*)d_in[8];
    const float* ms_W2     = (const float*)d_in[9];
    const float* ms_b2     = (const float*)d_in[10];
    const float* vg_Wq     = (const float*)d_in[11];
    const float* vg_Wk     = (const float*)d_in[12];
    const float* W_node_h  = (const float*)d_in[13];
    const float* W_rad_h   = (const float*)d_in[14];
    const float* W_prod_h  = (const float*)d_in[15];
    const int*   eidx      = (const int*)d_in[16];
    const int* src = eidx;
    const int* dst = eidx + CE;
    float* out = (float*)d_out;

    static int smem_set = 0;
    if (!smem_set) {
        cudaFuncSetAttribute(fused_gemms, cudaFuncAttributeMaxDynamicSharedMemorySize,
                             FUSED_SMEM);
        smem_set = 1;
    }

    void *p_hW, *p_upd, *p_hlocal, *p_counts, *p_offsets, *p_cursor, *p_eids, *p_m,
         *p_master, *p_rank, *p_adj, *p_arec, *p_hm, *p_posm, *p_q, *p_k, *p_hWh,
         *p_hhier, *p_updtf, *p_wpltf, *p_wphtf, *p_updmtf;
    cudaGetSymbolAddress(&p_hW, g_hW);
    cudaGetSymbolAddress(&p_upd, g_upd);
    cudaGetSymbolAddress(&p_hlocal, g_hlocal);
    cudaGetSymbolAddress(&p_counts, g_counts);
    cudaGetSymbolAddress(&p_offsets, g_offsets);
    cudaGetSymbolAddress(&p_cursor, g_cursor);
    cudaGetSymbolAddress(&p_eids, g_eids);
    cudaGetSymbolAddress(&p_m, g_m);
    cudaGetSymbolAddress(&p_master, g_master);
    cudaGetSymbolAddress(&p_rank, g_rank);
    cudaGetSymbolAddress(&p_adj, g_adj);
    cudaGetSymbolAddress(&p_arec, g_arec);
    cudaGetSymbolAddress(&p_hm, g_hm);
    cudaGetSymbolAddress(&p_posm, g_posm);
    cudaGetSymbolAddress(&p_q, g_q);
    cudaGetSymbolAddress(&p_k, g_k);
    cudaGetSymbolAddress(&p_hWh, g_hWh);
    cudaGetSymbolAddress(&p_hhier, g_hhier);
    cudaGetSymbolAddress(&p_updtf, g_updtf);
    cudaGetSymbolAddress(&p_wpltf, g_wpltf);
    cudaGetSymbolAddress(&p_wphtf, g_wphtf);
    cudaGetSymbolAddress(&p_updmtf, g_updmtf);

    // CSR build
    zero_int_kernel<<<CN / 256, 256>>>((int*)p_counts, CN);
    count_kernel<<<CE / 256, 256>>>(dst, (int*)p_counts);
    scan_kernel<<<1, 1024>>>((int*)p_counts, (int*)p_offsets, (int*)p_cursor);
    scatter_kernel<<<CE / 256, 256>>>(dst, (int*)p_cursor, (int*)p_eids);

    // weight tf32 pre-conversion
    f2tf_kernel<<<(CDOUT * CDOUT / 4 + 255) / 256, 256>>>(W_prod_l, (unsigned*)p_wpltf,
                                                          CDOUT * CDOUT / 4);
    f2tf_kernel<<<(CDOUT * CDOUT / 4 + 255) / 256, 256>>>(W_prod_h, (unsigned*)p_wphtf,
                                                          CDOUT * CDOUT / 4);

    // hW = h @ W_node_l (fp32)
    sgemm128<<<dim3(1, CN / 128), 256>>>(h, CF, W_node_l, CF, (float*)p_hW, CF, CF,
                                         (const float*)0, 0, 0);
    // edge message accumulation (fp32 + fused tf32 output)
    edge_accum_kernel<<<CN, 128>>>((const float*)p_hW, edge_sh, edge_fts, W_rad_l,
                                   src, (const int*)p_offsets, (const int*)p_eids,
                                   (float*)p_upd, (unsigned*)p_updtf);
    // fused: fp32 exact slice (cols 0..127, bit-identical) + tf32 TC (cols 128..1151)
    fused_gemms<<<1152, 256, FUSED_SMEM>>>(
        (const float*)p_upd, W_prod_l, (float*)p_hlocal, h,
        (const unsigned*)p_updtf, (const unsigned*)p_wpltf + CF, (float*)p_hlocal + CF);
    // gating MLP
    mlp_kernel<<<CN / 16, 128>>>((const float*)p_hlocal, ms_W1, ms_b1, ms_W2, ms_b2,
                                 (float*)p_m);
    // exact top-K + fused rank init/set + master-index output
    topk_kernel<<<1, 1024>>>((const float*)p_m, (int*)p_master, (int*)p_rank,
                             out + OFF_MI);
    // induced adjacency
    zero_u8_kernel<<<(CK * CK) / 256, 256>>>((unsigned char*)p_adj, CK * CK);
    adj_kernel<<<CE / 256, 256>>>(src, dst, (const int*)p_rank, (unsigned char*)p_adj);
    // gather masters
    gather_kernel<<<CK, 128>>>((const float*)p_hlocal, pos, (const int*)p_master,
                               (float*)p_hm, (float*)p_posm);
    // q / k projections (exact fp32)
    sgemm64<<<dim3(CDA / 64, CK / 64), 256>>>((const float*)p_hm, CDOUT, vg_Wq, CDA,
                                              (float*)p_q, CDA, CF);
    sgemm64<<<dim3(CDA / 64, CK / 64), 256>>>((const float*)p_hm, CDOUT, vg_Wk, CDA,
                                              (float*)p_k, CDA, CF);
    // attention -> A_virtual (tiled, K through smem)
    attn_kernel<<<CK / 16, 256>>>((const float*)p_q, (const float*)p_k, out + OFF_AV);
    // A_rec mask
    arec_kernel<<<(CK * CK) / 256, 256>>>(out + OFF_AV, (const unsigned char*)p_adj,
                                          (unsigned char*)p_arec);
    // hWh = h_m @ W_node_h (fp32, 32 blocks)
    sgemm64<<<dim3(CF / 64, CK / 64), 256>>>((const float*)p_hm, CDOUT,
                                             W_node_h, CF, (float*)p_hWh, CF, CDOUT);
    // masked geometry accumulation -> upd_m (tf32 bits)
    geom_kernel<<<CK, 128>>>((const float*)p_posm, (const float*)p_hWh,
                             (const unsigned char*)p_arec, W_rad_h,
                             (unsigned*)p_updmtf);
    // h_hier = upd_m @ W_prod_h + h_m (tf32 TC)
    tgemm128<<<dim3(CDOUT / 128, CK / 128), 256>>>(
        (const unsigned*)p_updmtf, CDOUT, (const unsigned*)p_wphtf, CDOUT,
        (float*)p_hhier, CDOUT, CDOUT, (const float*)p_hm, CDOUT);
    // final blend + m output
    blend_kernel<<<CN, 128>>>((const float*)p_hlocal, (const float*)p_hhier,
                              (const float*)p_m, (const int*)p_rank,
                              out, out + OFF_M);
}

// round 16
// speedup vs baseline: 1.2377x; 1.0284x over previous
#include <cuda_runtime.h>
#include <cuda_bf16.h>
#include <math.h>

#define CN 16384
#define CE 131072
#define CF 128
#define CL 9
#define CR 8
#define CDOUT 1152
#define CK 1024
#define CHID 64
#define CDA 64
#define CRCUT 5.0f
#define CEPS 1e-9f
#define FPI 3.14159265358979323846f

#define OFF_AV ((long long)CN * CDOUT)
#define OFF_M  (OFF_AV + (long long)CK * CK)
#define OFF_MI (OFF_M + CN)

// ---------------- device scratch ----------------
__device__ float g_hW[CN * CF];
__device__ float g_upd[CN * CDOUT];
__device__ float g_hlocal[CN * CDOUT];
__device__ int   g_counts[CN];
__device__ int   g_offsets[CN + 1];
__device__ int   g_cursor[CN];
__device__ int   g_eids[CE];
__device__ float g_m[CN];
__device__ int   g_master[CK];
__device__ int   g_rank[CN];
__device__ unsigned char g_adj[CK * CK];
__device__ unsigned char g_arec[CK * CK];
__device__ float g_hm[CK * CDOUT];
__device__ float g_posm[CK * 3];
__device__ float g_q[CK * CDA];
__device__ float g_k[CK * CDA];
__device__ float g_hWh[CK * CF];
__device__ float g_hhier[CK * CDOUT];
__device__ unsigned g_updtf[CN * CDOUT];
__device__ unsigned g_wpltf[CDOUT * CDOUT];
__device__ unsigned g_wphtf[CDOUT * CDOUT];
__device__ unsigned g_updmtf[CK * CDOUT];

// ---------------- utility ----------------
__global__ void zero_int_kernel(int* p, int n) {
    int i = blockIdx.x * blockDim.x + threadIdx.x;
    if (i < n) p[i] = 0;
}
__global__ void zero_u8_kernel(unsigned char* p, int n) {
    int i = blockIdx.x * blockDim.x + threadIdx.x;
    if (i < n) p[i] = 0;
}

__device__ __forceinline__ unsigned f2tf32(float f) {
    unsigned u;
    asm("cvt.rna.tf32.f32 %0, %1;" : "=r"(u) : "f"(f));
    return u;
}

__global__ void f2tf_kernel(const float* __restrict__ in, unsigned* __restrict__ out, int n4) {
    int i = blockIdx.x * blockDim.x + threadIdx.x;
    if (i < n4) {
        float4 v = ((const float4*)in)[i];
        uint4 u = make_uint4(f2tf32(v.x), f2tf32(v.y), f2tf32(v.z), f2tf32(v.w));
        ((uint4*)out)[i] = u;
    }
}

#define CP_ASYNC16(dst_u32, src_ptr) \
    asm volatile("cp.async.cg.shared.global [%0], [%1], 16;" :: "r"(dst_u32), "l"(src_ptr))
#define CP_COMMIT() asm volatile("cp.async.commit_group;" ::: "memory")
#define CP_WAIT1()  asm volatile("cp.async.wait_group 1;" ::: "memory")
#define CP_WAIT0()  asm volatile("cp.async.wait_group 0;" ::: "memory")

// ================= fused big GEMM (R13/R15 layout, unchanged) =================
#define FUSED_SMEM 56832

__global__ __launch_bounds__(256, 2) void fused_gemms(
    const float* __restrict__ Afp, const float* __restrict__ Bfp,
    float* __restrict__ Cfp, const float* __restrict__ addfp,
    const unsigned* __restrict__ Atf, const unsigned* __restrict__ Btf,
    float* __restrict__ Ctf)
{
    extern __shared__ __align__(16) char smem_raw[];
    const int tid = threadIdx.x;

    if (blockIdx.x < 128) {
        typedef float AsT[8][128];
        typedef float BsT[8][128];
        AsT* As = (AsT*)smem_raw;
        BsT* Bs = (BsT*)(smem_raw + 2 * 8 * 128 * 4);
        const int tx = tid & 15, ty = tid >> 4;
        const int m0 = blockIdx.x * 128;
        const int lda = CDOUT, ldb = CDOUT, ldc = CDOUT, ldadd = CF;
        const int Ksize = CDOUT;

        float acc[8][8];
#pragma unroll
        for (int i = 0; i < 8; i++)
#pragma unroll
            for (int j = 0; j < 8; j++) acc[i][j] = 0.f;

        const int arow = tid >> 1;
        const int akc  = (tid & 1) * 4;
        const int brow = tid >> 5;
        const int bcol = (tid & 31) * 4;

        float4 av = *(const float4*)(Afp + (long long)(m0 + arow) * lda + akc);
        float4 bv = *(const float4*)(Bfp + (long long)brow * ldb + bcol);
        As[0][akc + 0][arow] = av.x; As[0][akc + 1][arow] = av.y;
        As[0][akc + 2][arow] = av.z; As[0][akc + 3][arow] = av.w;
        *(float4*)&Bs[0][brow][bcol] = bv;
        __syncthreads();

        const int KT = Ksize >> 3;
        for (int kt = 0; kt < KT; ++kt) {
            int cur = kt & 1;
            if (kt + 1 < KT) {
                int k0 = (kt + 1) << 3;
                av = *(const float4*)(Afp + (long long)(m0 + arow) * lda + k0 + akc);
                bv = *(const float4*)(Bfp + (long long)(k0 + brow) * ldb + bcol);
            }
#pragma unroll
            for (int kk = 0; kk < 8; ++kk) {
                float a[8], b[8];
                *(float4*)a       = *(const float4*)&As[cur][kk][ty * 4];
                *(float4*)(a + 4) = *(const float4*)&As[cur][kk][ty * 4 + 64];
                *(float4*)b       = *(const float4*)&Bs[cur][kk][tx * 4];
                *(float4*)(b + 4) = *(const float4*)&Bs[cur][kk][tx * 4 + 64];
#pragma unroll
                for (int i = 0; i < 8; i++)
#pragma unroll
                    for (int j = 0; j < 8; j++) acc[i][j] += a[i] * b[j];
            }
            if (kt + 1 < KT) {
                int nxt = cur ^ 1;
                As[nxt][akc + 0][arow] = av.x; As[nxt][akc + 1][arow] = av.y;
                As[nxt][akc + 2][arow] = av.z; As[nxt][akc + 3][arow] = av.w;
                *(float4*)&Bs[nxt][brow][bcol] = bv;
            }
            __syncthreads();
        }

#pragma unroll
        for (int i = 0; i < 8; i++) {
            int row = m0 + ty * 4 + (i & 3) + (i >> 2) * 64;
#pragma unroll
            for (int j = 0; j < 8; j++) {
                int col = tx * 4 + (j & 3) + (j >> 2) * 64;
                float v = acc[i][j];
                if (col < CF) v += addfp[(long long)row * ldadd + col];
                Cfp[(long long)row * ldc + col] = v;
            }
        }
    } else {
        typedef unsigned AsTT[128][20];
        typedef unsigned BsTT[16][136];
        AsTT* As = (AsTT*)smem_raw;
        BsTT* Bs = (BsTT*)(smem_raw + 3 * 128 * 20 * 4);
        const int b = blockIdx.x - 128;
        const int lane = tid & 31, wid = tid >> 5;
        const int wm = wid >> 2, wn = wid & 3;
        const int m0 = (b >> 3) * 128, n0 = (b & 7) * 128;
        const int g = lane >> 2, tq = lane & 3;
        const int lda = CDOUT, ldb = CDOUT, ldc = CDOUT;

        float acc[4][4][4];
#pragma unroll
        for (int i = 0; i < 4; i++)
#pragma unroll
            for (int j = 0; j < 4; j++)
#pragma unroll
                for (int c = 0; c < 4; c++) acc[i][j][c] = 0.f;

        const int a_r = tid >> 2, a_c = (tid & 3) * 4;
        const int b_r = tid >> 5, b_c = (tid & 31) * 4;
        const unsigned* Aptr = Atf + (long long)(m0 + a_r) * lda + a_c;
        const unsigned* Bptr = Btf + (long long)b_r * ldb + n0 + b_c;

        unsigned sA0[3], sA1[3], sB0[3], sB1[3];
#pragma unroll
        for (int s = 0; s < 3; s++) {
            sA0[s] = (unsigned)__cvta_generic_to_shared(&As[s][a_r][a_c]);
            sA1[s] = (unsigned)__cvta_generic_to_shared(&As[s][a_r + 64][a_c]);
            sB0[s] = (unsigned)__cvta_generic_to_shared(&Bs[s][b_r][b_c]);
            sB1[s] = (unsigned)__cvta_generic_to_shared(&Bs[s][b_r + 8][b_c]);
        }

        const int KT = CDOUT >> 4;
        {
            CP_ASYNC16(sA0[0], Aptr);
            CP_ASYNC16(sA1[0], Aptr + (long long)64 * lda);
            CP_ASYNC16(sB0[0], Bptr);
            CP_ASYNC16(sB1[0], Bptr + (long long)8 * ldb);
            CP_COMMIT();
            CP_ASYNC16(sA0[1], Aptr + 16);
            CP_ASYNC16(sA1[1], Aptr + 16 + (long long)64 * lda);
            CP_ASYNC16(sB0[1], Bptr + (long long)16 * ldb);
            CP_ASYNC16(sB1[1], Bptr + (long long)24 * ldb);
            CP_COMMIT();
        }

        int cur = 0;
        for (int kt = 0; kt < KT; ++kt) {
            if (kt + 1 < KT) { CP_WAIT1(); } else { CP_WAIT0(); }
            __syncthreads();
            if (kt + 2 < KT) {
                int s = cur + 2; if (s >= 3) s -= 3;
                const unsigned* Ap = Aptr + (kt + 2) * 16;
                const unsigned* Bp = Bptr + (long long)((kt + 2) * 16) * ldb;
                CP_ASYNC16(sA0[s], Ap);
                CP_ASYNC16(sA1[s], Ap + (long long)64 * lda);
                CP_ASYNC16(sB0[s], Bp);
                CP_ASYNC16(sB1[s], Bp + (long long)8 * ldb);
                CP_COMMIT();
            }
#pragma unroll
            for (int kk = 0; kk < 16; kk += 8) {
                unsigned af[4][4];
#pragma unroll
                for (int mi = 0; mi < 4; mi++) {
                    int r = wm * 64 + mi * 16 + g;
                    af[mi][0] = As[cur][r][kk + tq];
                    af[mi][1] = As[cur][r + 8][kk + tq];
                    af[mi][2] = As[cur][r][kk + tq + 4];
                    af[mi][3] = As[cur][r + 8][kk + tq + 4];
                }
                unsigned bf[4][2];
#pragma unroll
                for (int nj = 0; nj < 4; nj++) {
                    int cidx = wn * 32 + nj * 8 + g;
                    bf[nj][0] = Bs[cur][kk + tq][cidx];
                    bf[nj][1] = Bs[cur][kk + tq + 4][cidx];
                }
#pragma unroll
                for (int mi = 0; mi < 4; mi++)
#pragma unroll
                    for (int nj = 0; nj < 4; nj++)
                        asm volatile(
                            "mma.sync.aligned.m16n8k8.row.col.f32.tf32.tf32.f32 "
                            "{%0,%1,%2,%3}, {%4,%5,%6,%7}, {%8,%9}, {%0,%1,%2,%3};"
                            : "+f"(acc[mi][nj][0]), "+f"(acc[mi][nj][1]),
                              "+f"(acc[mi][nj][2]), "+f"(acc[mi][nj][3])
                            : "r"(af[mi][0]), "r"(af[mi][1]), "r"(af[mi][2]), "r"(af[mi][3]),
                              "r"(bf[nj][0]), "r"(bf[nj][1]));
            }
            cur = (cur + 1 == 3) ? 0 : cur + 1;
        }

#pragma unroll
        for (int mi = 0; mi < 4; mi++) {
            int r = wm * 64 + mi * 16 + g;
#pragma unroll
            for (int nj = 0; nj < 4; nj++) {
                int c = wn * 32 + nj * 8 + tq * 2;
                long long i0 = (long long)(m0 + r) * ldc + n0 + c;
                long long i1 = (long long)(m0 + r + 8) * ldc + n0 + c;
                *(float2*)(Ctf + i0) = make_float2(acc[mi][nj][0], acc[mi][nj][1]);
                *(float2*)(Ctf + i1) = make_float2(acc[mi][nj][2], acc[mi][nj][3]);
            }
        }
    }
}

// ---------------- standalone tf32 GEMM (hhier) ----------------
__global__ __launch_bounds__(256) void tgemm128(
    const unsigned* __restrict__ A, int lda,
    const unsigned* __restrict__ B, int ldb,
    float* __restrict__ C, int ldc, int Ksize,
    const float* __restrict__ addsrc, int ldadd)
{
    __shared__ __align__(16) unsigned As[3][128][20];
    __shared__ __align__(16) unsigned Bs[3][16][136];
    const int tid = threadIdx.x;
    const int lane = tid & 31, wid = tid >> 5;
    const int wm = wid >> 2, wn = wid & 3;
    const int m0 = blockIdx.y * 128, n0 = blockIdx.x * 128;
    const int g = lane >> 2, tq = lane & 3;

    float acc[4][4][4];
#pragma unroll
    for (int i = 0; i < 4; i++)
#pragma unroll
        for (int j = 0; j < 4; j++)
#pragma unroll
            for (int c = 0; c < 4; c++) acc[i][j][c] = 0.f;

    const int a_r = tid >> 2, a_c = (tid & 3) * 4;
    const int b_r = tid >> 5, b_c = (tid & 31) * 4;
    const unsigned* Aptr = A + (long long)(m0 + a_r) * lda + a_c;
    const unsigned* Bptr = B + (long long)b_r * ldb + n0 + b_c;

    unsigned sA0[3], sA1[3], sB0[3], sB1[3];
#pragma unroll
    for (int s = 0; s < 3; s++) {
        sA0[s] = (unsigned)__cvta_generic_to_shared(&As[s][a_r][a_c]);
        sA1[s] = (unsigned)__cvta_generic_to_shared(&As[s][a_r + 64][a_c]);
        sB0[s] = (unsigned)__cvta_generic_to_shared(&Bs[s][b_r][b_c]);
        sB1[s] = (unsigned)__cvta_generic_to_shared(&Bs[s][b_r + 8][b_c]);
    }

    const int KT = Ksize >> 4;
    {
        CP_ASYNC16(sA0[0], Aptr);
        CP_ASYNC16(sA1[0], Aptr + (long long)64 * lda);
        CP_ASYNC16(sB0[0], Bptr);
        CP_ASYNC16(sB1[0], Bptr + (long long)8 * ldb);
        CP_COMMIT();
        CP_ASYNC16(sA0[1], Aptr + 16);
        CP_ASYNC16(sA1[1], Aptr + 16 + (long long)64 * lda);
        CP_ASYNC16(sB0[1], Bptr + (long long)16 * ldb);
        CP_ASYNC16(sB1[1], Bptr + (long long)24 * ldb);
        CP_COMMIT();
    }

    int cur = 0;
    for (int kt = 0; kt < KT; ++kt) {
        if (kt + 1 < KT) { CP_WAIT1(); } else { CP_WAIT0(); }
        __syncthreads();
        if (kt + 2 < KT) {
            int s = cur + 2; if (s >= 3) s -= 3;
            const unsigned* Ap = Aptr + (kt + 2) * 16;
            const unsigned* Bp = Bptr + (long long)((kt + 2) * 16) * ldb;
            CP_ASYNC16(sA0[s], Ap);
            CP_ASYNC16(sA1[s], Ap + (long long)64 * lda);
            CP_ASYNC16(sB0[s], Bp);
            CP_ASYNC16(sB1[s], Bp + (long long)8 * ldb);
            CP_COMMIT();
        }
#pragma unroll
        for (int kk = 0; kk < 16; kk += 8) {
            unsigned af[4][4];
#pragma unroll
            for (int mi = 0; mi < 4; mi++) {
                int r = wm * 64 + mi * 16 + g;
                af[mi][0] = As[cur][r][kk + tq];
                af[mi][1] = As[cur][r + 8][kk + tq];
                af[mi][2] = As[cur][r][kk + tq + 4];
                af[mi][3] = As[cur][r + 8][kk + tq + 4];
            }
            unsigned bf[4][2];
#pragma unroll
            for (int nj = 0; nj < 4; nj++) {
                int cidx = wn * 32 + nj * 8 + g;
                bf[nj][0] = Bs[cur][kk + tq][cidx];
                bf[nj][1] = Bs[cur][kk + tq + 4][cidx];
            }
#pragma unroll
            for (int mi = 0; mi < 4; mi++)
#pragma unroll
                for (int nj = 0; nj < 4; nj++)
                    asm volatile(
                        "mma.sync.aligned.m16n8k8.row.col.f32.tf32.tf32.f32 "
                        "{%0,%1,%2,%3}, {%4,%5,%6,%7}, {%8,%9}, {%0,%1,%2,%3};"
                        : "+f"(acc[mi][nj][0]), "+f"(acc[mi][nj][1]),
                          "+f"(acc[mi][nj][2]), "+f"(acc[mi][nj][3])
                        : "r"(af[mi][0]), "r"(af[mi][1]), "r"(af[mi][2]), "r"(af[mi][3]),
                          "r"(bf[nj][0]), "r"(bf[nj][1]));
        }
        cur = (cur + 1 == 3) ? 0 : cur + 1;
    }

#pragma unroll
    for (int mi = 0; mi < 4; mi++) {
        int r = wm * 64 + mi * 16 + g;
#pragma unroll
        for (int nj = 0; nj < 4; nj++) {
            int c = wn * 32 + nj * 8 + tq * 2;
            long long i0 = (long long)(m0 + r) * ldc + n0 + c;
            long long i1 = (long long)(m0 + r + 8) * ldc + n0 + c;
            float2 v0 = make_float2(acc[mi][nj][0], acc[mi][nj][1]);
            float2 v1 = make_float2(acc[mi][nj][2], acc[mi][nj][3]);
            if (addsrc) {
                long long a0 = (long long)(m0 + r) * ldadd + n0 + c;
                long long a1 = (long long)(m0 + r + 8) * ldadd + n0 + c;
                v0.x += addsrc[a0]; v0.y += addsrc[a0 + 1];
                v1.x += addsrc[a1]; v1.y += addsrc[a1 + 1];
            }
            *(float2*)(C + i0) = v0;
            *(float2*)(C + i1) = v1;
        }
    }
}

// ---------------- SGEMM 128x128 fp32 (hW) ----------------
__global__ __launch_bounds__(256) void sgemm128(
    const float* __restrict__ A, int lda,
    const float* __restrict__ B, int ldb,
    float* __restrict__ C, int ldc, int Ksize,
    const float* __restrict__ addsrc, int ldadd, int addcols)
{
    __shared__ float As[2][8][128];
    __shared__ float Bs[2][8][128];
    const int tid = threadIdx.x;
    const int tx = tid & 15, ty = tid >> 4;
    const int m0 = blockIdx.y * 128;
    const int n0 = blockIdx.x * 128;

    float acc[8][8];
#pragma unroll
    for (int i = 0; i < 8; i++)
#pragma unroll
        for (int j = 0; j < 8; j++) acc[i][j] = 0.f;

    const int arow = tid >> 1;
    const int akc  = (tid & 1) * 4;
    const int brow = tid >> 5;
    const int bcol = (tid & 31) * 4;

    float4 av = *(const float4*)(A + (long long)(m0 + arow) * lda + akc);
    float4 bv = *(const float4*)(B + (long long)brow * ldb + n0 + bcol);
    As[0][akc + 0][arow] = av.x; As[0][akc + 1][arow] = av.y;
    As[0][akc + 2][arow] = av.z; As[0][akc + 3][arow] = av.w;
    *(float4*)&Bs[0][brow][bcol] = bv;
    __syncthreads();

    const int KT = Ksize >> 3;
    for (int kt = 0; kt < KT; ++kt) {
        int cur = kt & 1;
        if (kt + 1 < KT) {
            int k0 = (kt + 1) << 3;
            av = *(const float4*)(A + (long long)(m0 + arow) * lda + k0 + akc);
            bv = *(const float4*)(B + (long long)(k0 + brow) * ldb + n0 + bcol);
        }
#pragma unroll
        for (int kk = 0; kk < 8; ++kk) {
            float a[8], b[8];
            *(float4*)a       = *(const float4*)&As[cur][kk][ty * 4];
            *(float4*)(a + 4) = *(const float4*)&As[cur][kk][ty * 4 + 64];
            *(float4*)b       = *(const float4*)&Bs[cur][kk][tx * 4];
            *(float4*)(b + 4) = *(const float4*)&Bs[cur][kk][tx * 4 + 64];
#pragma unroll
            for (int i = 0; i < 8; i++)
#pragma unroll
                for (int j = 0; j < 8; j++) acc[i][j] += a[i] * b[j];
        }
        if (kt + 1 < KT) {
            int nxt = cur ^ 1;
            As[nxt][akc + 0][arow] = av.x; As[nxt][akc + 1][arow] = av.y;
            As[nxt][akc + 2][arow] = av.z; As[nxt][akc + 3][arow] = av.w;
            *(float4*)&Bs[nxt][brow][bcol] = bv;
        }
        __syncthreads();
    }

#pragma unroll
    for (int i = 0; i < 8; i++) {
        int row = m0 + ty * 4 + (i & 3) + (i >> 2) * 64;
#pragma unroll
        for (int j = 0; j < 8; j++) {
            int col = n0 + tx * 4 + (j & 3) + (j >> 2) * 64;
            float v = acc[i][j];
            if (col < addcols) v += addsrc[(long long)row * ldadd + col];
            C[(long long)row * ldc + col] = v;
        }
    }
}

// ---------------- SGEMM 64x64 fp32 ----------------
__global__ __launch_bounds__(256) void sgemm64(
    const float* __restrict__ A, int lda,
    const float* __restrict__ B, int ldb,
    float* __restrict__ C, int ldc, int Ksize)
{
    __shared__ float As[16][64];
    __shared__ float Bs[16][64];
    const int tid = threadIdx.x;
    const int tx = tid & 15, ty = tid >> 4;
    const int m0 = blockIdx.y * 64, n0 = blockIdx.x * 64;
    float acc[4][4];
#pragma unroll
    for (int i = 0; i < 4; i++)
#pragma unroll
        for (int j = 0; j < 4; j++) acc[i][j] = 0.f;

    const int arow = tid >> 2, akc = (tid & 3) * 4;
    const int brow = tid >> 4, bcol = (tid & 15) * 4;
    const int KT = Ksize >> 4;
    for (int kt = 0; kt < KT; ++kt) {
        int k0 = kt << 4;
        float4 av = *(const float4*)(A + (long long)(m0 + arow) * lda + k0 + akc);
        float4 bv = *(const float4*)(B + (long long)(k0 + brow) * ldb + n0 + bcol);
        __syncthreads();
        As[akc + 0][arow] = av.x; As[akc + 1][arow] = av.y;
        As[akc + 2][arow] = av.z; As[akc + 3][arow] = av.w;
        *(float4*)&Bs[brow][bcol] = bv;
        __syncthreads();
#pragma unroll
        for (int kk = 0; kk < 16; ++kk) {
            float4 a4 = *(const float4*)&As[kk][ty * 4];
            float4 b4 = *(const float4*)&Bs[kk][tx * 4];
            float a[4] = {a4.x, a4.y, a4.z, a4.w};
            float b[4] = {b4.x, b4.y, b4.z, b4.w};
#pragma unroll
            for (int i = 0; i < 4; i++)
#pragma unroll
                for (int j = 0; j < 4; j++) acc[i][j] += a[i] * b[j];
        }
    }
#pragma unroll
    for (int i = 0; i < 4; i++) {
        int row = m0 + ty * 4 + i;
#pragma unroll
        for (int j = 0; j < 4; j++)
            C[(long long)row * ldc + n0 + tx * 4 + j] = acc[i][j];
    }
}

// ---------------- CSR build ----------------
__global__ void count_kernel(const int* __restrict__ dstArr, int* __restrict__ counts) {
    int e = blockIdx.x * blockDim.x + threadIdx.x;
    if (e < CE) atomicAdd(&counts[dstArr[e]], 1);
}
__global__ __launch_bounds__(1024) void scan_kernel(
    const int* __restrict__ counts, int* __restrict__ offsets, int* __restrict__ cursor)
{
    __shared__ int s[1024];
    int tid = threadIdx.x;
    int base = tid * 16;
    int loc[16]; int sum = 0;
#pragma unroll
    for (int i = 0; i < 16; i++) { loc[i] = sum; sum += counts[base + i]; }
    s[tid] = sum; __syncthreads();
    for (int off = 1; off < 1024; off <<= 1) {
        int x = (tid >= off) ? s[tid - off] : 0;
        __syncthreads();
        s[tid] += x;
        __syncthreads();
    }
    int excl = s[tid] - sum;
#pragma unroll
    for (int i = 0; i < 16; i++) { int o = excl + loc[i]; offsets[base + i] = o; cursor[base + i] = o; }
    if (tid == 1023) offsets[CN] = excl + sum;
}
__global__ void scatter_kernel(const int* __restrict__ dstArr, int* __restrict__ cursor,
                               int* __restrict__ eids) {
    int e = blockIdx.x * blockDim.x + threadIdx.x;
    if (e < CE) { int p = atomicAdd(&cursor[dstArr[e]], 1); eids[p] = e; }
}

// ---------------- edge accumulation (fused tf32 output) ----------------
__global__ __launch_bounds__(128) void edge_accum_kernel(
    const float* __restrict__ hW, const float* __restrict__ edge_sh,
    const float* __restrict__ edge_feats, const float* __restrict__ W_rad_l,
    const int* __restrict__ srcArr, const int* __restrict__ offsets,
    const int* __restrict__ eids, float* __restrict__ upd,
    unsigned* __restrict__ updtf)
{
    __shared__ float Wrl[CR][CF];
    __shared__ int list[1024];
    const int n = blockIdx.x;
    const int tid = threadIdx.x;
#pragma unroll
    for (int r = 0; r < CR; ++r) Wrl[r][tid] = W_rad_l[r * CF + tid];
    const int s0 = offsets[n], s1 = offsets[n + 1];
    const int deg = s1 - s0;
    const int use = (deg <= 1024) ? deg : 0;
    for (int i = tid; i < use; i += 128) list[i] = eids[s0 + i];
    __syncthreads();
    if (tid == 0 && use > 1) {
        for (int a = 1; a < use; a++) {
            int v = list[a]; int b = a - 1;
            while (b >= 0 && list[b] > v) { list[b + 1] = list[b]; b--; }
            list[b + 1] = v;
        }
    }
    __syncthreads();
    float acc[CL];
#pragma unroll
    for (int l = 0; l < CL; l++) acc[l] = 0.f;
    for (int q = 0; q < deg; ++q) {
        int e = (deg <= 1024) ? list[q] : eids[s0 + q];
        const float4* ef4 = (const float4*)(edge_feats + (long long)e * CR);
        float4 e0 = __ldg(&ef4[0]);
        float4 e1 = __ldg(&ef4[1]);
        float rs = e0.x * Wrl[0][tid] + e0.y * Wrl[1][tid] + e0.z * Wrl[2][tid] + e0.w * Wrl[3][tid]
                 + e1.x * Wrl[4][tid] + e1.y * Wrl[5][tid] + e1.z * Wrl[6][tid] + e1.w * Wrl[7][tid];
        int s = __ldg(&srcArr[e]);
        float t = __ldg(&hW[(long long)s * CF + tid]) * rs;
#pragma unroll
        for (int l = 0; l < CL; l++) acc[l] += __ldg(&edge_sh[(long long)e * CL + l]) * t;
    }
    long long obase = (long long)n * CDOUT + tid;
#pragma unroll
    for (int l = 0; l < CL; l++) {
        upd[obase + l * CF] = acc[l];
        updtf[obase + l * CF] = f2tf32(acc[l]);
    }
}

// ---------------- gating MLP ----------------
__global__ __launch_bounds__(128) void mlp_kernel(
    const float* __restrict__ hlocal,
    const float* __restrict__ W1, const float* __restrict__ b1,
    const float* __restrict__ W2, const float* __restrict__ b2,
    float* __restrict__ mout)
{
    __shared__ float W1s[CF][CHID];
    __shared__ float hs[16][CF];
    __shared__ float hid[16][CHID];
    const int tid = threadIdx.x;
    const int n0 = blockIdx.x * 16;
    for (int i = tid; i < CF * CHID; i += 128) W1s[i / CHID][i % CHID] = W1[i];
#pragma unroll
    for (int rr = 0; rr < 16; ++rr) hs[rr][tid] = hlocal[(long long)(n0 + rr) * CDOUT + tid];
    __syncthreads();
    for (int idx = tid; idx < 16 * CHID; idx += 128) {
        int rr = idx >> 6, j = idx & 63;
        float a = b1[j];
#pragma unroll 8
        for (int k2 = 0; k2 < CF; k2++) a += hs[rr][k2] * W1s[k2][j];
        hid[rr][j] = a > 0.f ? a : 0.f;
    }
    __syncthreads();
    int rr = tid >> 3, part = tid & 7;
    float sacc = 0.f;
    for (int j = part; j < CHID; j += 8) sacc += hid[rr][j] * W2[j];
    for (int o = 4; o > 0; o >>= 1) sacc += __shfl_down_sync(0xffffffffu, sacc, o, 8);
    if (part == 0) {
        float x = sacc + b2[0];
        mout[n0 + rr] = 1.f / (1.f + expf(-x));
    }
}

// ---------------- exact top-K + rank/outMi fused ----------------
__device__ __forceinline__ unsigned mapf(float f) {
    unsigned u = __float_as_uint(f);
    return (u & 0x80000000u) ? ~u : (u | 0x80000000u);
}
__global__ __launch_bounds__(1024) void topk_kernel(const float* __restrict__ m,
                                                    int* __restrict__ master,
                                                    int* __restrict__ rank,
                                                    float* __restrict__ outMi)
{
    __shared__ unsigned hist[256];
    __shared__ unsigned sPref; __shared__ int sWant;
    __shared__ int wsum[32], woff[32];
    __shared__ int s_eqRun, s_chRun;
    const int tid = threadIdx.x;
    const int lane = tid & 31, wi = tid >> 5;
    unsigned prefix = 0; int want = CK;
    for (int shift = 24; shift >= 0; shift -= 8) {
        if (tid < 256) hist[tid] = 0u;
        __syncthreads();
        for (int i = tid; i < CN; i += 1024) {
            unsigned key = mapf(m[i]);
            if (shift == 24 || (key >> (shift + 8)) == prefix)
                atomicAdd(&hist[(key >> shift) & 255], 1u);
        }
        __syncthreads();
        if (tid == 0) {
            int w = want; int b = 255;
            for (int d = 255; d >= 0; d--) {
                if ((int)hist[d] >= w) { b = d; break; }
                w -= (int)hist[d];
            }
            sPref = (prefix << 8) | (unsigned)b; sWant = w;
        }
        __syncthreads();
        prefix = sPref; want = sWant;
        __syncthreads();
    }
    const unsigned T = prefix; const int needEq = want;
    if (tid == 0) { s_eqRun = 0; s_chRun = 0; }
    __syncthreads();
    for (int base = 0; base < CN; base += 1024) {
        int i = base + tid;
        unsigned key = mapf(m[i]);
        int isG = key > T;
        int isE = key == T;
        unsigned em = __ballot_sync(0xffffffffu, isE);
        if (lane == 0) wsum[wi] = __popc(em);
        __syncthreads();
        if (wi == 0) {
            int v = wsum[lane];
#pragma unroll
            for (int o = 1; o < 32; o <<= 1) {
                int t = __shfl_up_sync(0xffffffffu, v, o);
                if (lane >= o) v += t;
            }
            woff[lane] = v;
        }
        __syncthreads();
        int eqRank = s_eqRun + (wi ? woff[wi - 1] : 0) + __popc(em & ((1u << lane) - 1u));
        int chunkEq = woff[31];
        int chosen = isG || (isE && eqRank < needEq);
        unsigned cm = __ballot_sync(0xffffffffu, chosen);
        if (lane == 0) wsum[wi] = __popc(cm);
        __syncthreads();
        if (wi == 0) {
            int v = wsum[lane];
#pragma unroll
            for (int o = 1; o < 32; o <<= 1) {
                int t = __shfl_up_sync(0xffffffffu, v, o);
                if (lane >= o) v += t;
            }
            woff[lane] = v;
        }
        __syncthreads();
        int pos = s_chRun + (wi ? woff[wi - 1] : 0) + __popc(cm & ((1u << lane) - 1u));
        int chunkCh = woff[31];
        if (chosen && pos < CK) master[pos] = i;
        __syncthreads();
        if (tid == 0) { s_eqRun += chunkEq; s_chRun += chunkCh; }
        __syncthreads();
    }
    for (int i = tid; i < CN; i += 1024) rank[i] = CK;
    __syncthreads();
    if (tid < CK) {
        int n = master[tid];
        rank[n] = tid;
        outMi[tid] = (float)n;
    }
}

__global__ void adj_kernel(const int* __restrict__ src, const int* __restrict__ dst,
                           const int* __restrict__ rank, unsigned char* __restrict__ adj) {
    int e = blockIdx.x * blockDim.x + threadIdx.x;
    if (e < CE) {
        int rs = rank[src[e]], rd = rank[dst[e]];
        if (rs < CK && rd < CK) adj[(long long)rs * CK + rd] = 1;
    }
}

__global__ __launch_bounds__(128) void gather_kernel(
    const float* __restrict__ hlocal, const float* __restrict__ pos,
    const int* __restrict__ master, float* __restrict__ hm, float* __restrict__ posm)
{
    int i = blockIdx.x, tid = threadIdx.x;
    int n = master[i];
#pragma unroll
    for (int l = 0; l < CL; l++)
        hm[(long long)i * CDOUT + l * CF + tid] = hlocal[(long long)n * CDOUT + l * CF + tid];
    if (tid < 3) posm[i * 3 + tid] = pos[n * 3 + tid];
}

// ---------------- attention (R15, tiled K) ----------------
__global__ __launch_bounds__(256) void attn_kernel(const float* __restrict__ q,
                                                   const float* __restrict__ k,
                                                   float* __restrict__ AV) {
    __shared__ float qs[16][CDA + 1];
    __shared__ float ks[128][CDA + 1];
    const int i0 = blockIdx.x * 16;
    const int tid = threadIdx.x;
    for (int idx = tid; idx < 16 * CDA; idx += 256)
        qs[idx >> 6][idx & 63] = q[(long long)(i0 + (idx >> 6)) * CDA + (idx & 63)];
    const int il = tid >> 4;
    const int jo = tid & 15;
    for (int jt = 0; jt < CK; jt += 128) {
        __syncthreads();
        for (int idx = tid; idx < 128 * CDA; idx += 256) {
            int r = idx >> 6, c = idx & 63;
            ks[r][c] = k[(long long)(jt + r) * CDA + c];
        }
        __syncthreads();
#pragma unroll 1
        for (int jj = 0; jj < 8; jj++) {
            int j = jo + jj * 16;
            float d = 0.f;
#pragma unroll
            for (int c = 0; c < CDA; c++) d += qs[il][c] * ks[j][c];
            float a = 1.f / (1.f + expf(-d * 0.125f));
            AV[(long long)(i0 + il) * CK + jt + j] = (a > 0.5f) ? a : 0.f;
        }
    }
}

// ---------------- A_rec mask: 32x32 tiles, coalesced transposes ----------------
__global__ __launch_bounds__(256) void arec_kernel(
    const float* __restrict__ AV, const unsigned char* __restrict__ adj,
    unsigned char* __restrict__ arec)
{
    __shared__ float avT[32][33];
    __shared__ unsigned char adT[32][33];
    const int bi = blockIdx.y, bj = blockIdx.x;
    const int tx = threadIdx.x & 31, ty = threadIdx.x >> 5;  // 8 rows per pass
    for (int r = ty; r < 32; r += 8) {
        // row j = bj*32+r of AV/adj, cols i = bi*32+tx  (coalesced)
        avT[r][tx] = AV[(long long)(bj * 32 + r) * CK + bi * 32 + tx];
        adT[r][tx] = adj[(long long)(bj * 32 + r) * CK + bi * 32 + tx];
    }
    __syncthreads();
    for (int r = ty; r < 32; r += 8) {
        int i = bi * 32 + r, j = bj * 32 + tx;
        unsigned char v = 0;
        if (i != j) {
            if (adT[tx][r]) v = 1;                                        // adj[j][i]
            else if (avT[tx][r] > 0.f ||                                  // AV[j][i]
                     AV[(long long)i * CK + j] > 0.f) v = 1;              // AV[i][j] (coalesced)
        }
        arec[(long long)i * CK + j] = v;
    }
}

// ---------------- geometry accumulation: 128-wide chunks, parallel setup ----------------
// Per-thread accumulation order over j identical to the 16-chunk version -> bit-identical.
__global__ __launch_bounds__(128) void geom_kernel(
    const float* __restrict__ posm, const float* __restrict__ hWh,
    const unsigned char* __restrict__ arec, const float* __restrict__ Wrh_g,
    unsigned* __restrict__ updmtf)
{
    __shared__ float Wrh[CR][CF];
    __shared__ float shv[128][CL];
    __shared__ float radv[128][CR];
    __shared__ unsigned char act[128];
    const int i = blockIdx.x, tid = threadIdx.x;
#pragma unroll
    for (int r = 0; r < CR; r++) Wrh[r][tid] = Wrh_g[r * CF + tid];
    const float px = posm[i * 3], py = posm[i * 3 + 1], pz = posm[i * 3 + 2];
    float acc[CL];
#pragma unroll
    for (int l = 0; l < CL; l++) acc[l] = 0.f;

    for (int j0 = 0; j0 < CK; j0 += 128) {
        __syncthreads();
        {
            int j = j0 + tid;
            int a = arec[(long long)i * CK + j];
            act[tid] = (unsigned char)a;
            if (a) {
                float vx = posm[j * 3] - px, vy = posm[j * 3 + 1] - py, vz = posm[j * 3 + 2] - pz;
                float rr = sqrtf(vx * vx + vy * vy + vz * vz);
                float inv = 1.f / fmaxf(rr, CEPS);
                float x = vx * inv, y = vy * inv, z = vz * inv;
                shv[tid][0] = 1.f; shv[tid][1] = x; shv[tid][2] = y; shv[tid][3] = z;
                shv[tid][4] = x * y; shv[tid][5] = y * z; shv[tid][6] = 3.f * z * z - 1.f;
                shv[tid][7] = x * z; shv[tid][8] = x * x - y * y;
                float c = sqrtf(2.f / CRCUT);
                float invr = 1.f / fmaxf(rr, CEPS);
#pragma unroll
                for (int n2 = 1; n2 <= CR; n2++)
                    radv[tid][n2 - 1] = c * sinf((float)n2 * FPI * rr / CRCUT) * invr;
            }
        }
        __syncthreads();
#pragma unroll 1
        for (int jj = 0; jj < 128; jj++) {
            if (!act[jj]) continue;
            int j = j0 + jj;
            float rw = 0.f;
#pragma unroll
            for (int r = 0; r < CR; r++) rw += radv[jj][r] * Wrh[r][tid];
            float t = hWh[(long long)j * CF + tid] * rw;
#pragma unroll
            for (int l = 0; l < CL; l++) acc[l] += shv[jj][l] * t;
        }
    }
    long long ob = (long long)i * CDOUT + tid;
#pragma unroll
    for (int l = 0; l < CL; l++) updmtf[ob + l * CF] = f2tf32(acc[l]);
}

__global__ __launch_bounds__(128) void blend_kernel(
    const float* __restrict__ hlocal, const float* __restrict__ hhier,
    const float* __restrict__ m, const int* __restrict__ rank,
    float* __restrict__ out, float* __restrict__ outm)
{
    int n = blockIdx.x, tid = threadIdx.x;
    float mv = m[n]; int rk = rank[n];
    long long b = (long long)n * CDOUT + tid;
#pragma unroll
    for (int l = 0; l < CL; l++) {
        float hl = hlocal[b + l * CF];
        float he = (rk < CK) ? hhier[(long long)rk * CDOUT + l * CF + tid] : 0.f;
        out[b + l * CF] = (1.f - mv) * hl + mv * he;
    }
    if (tid == 0) outm[n] = mv;
}

// ---------------- launch ----------------
extern "C" void kernel_launch(void* const* d_in, const int* in_sizes, int n_in,
                              void* d_out, int out_size) {
    const float* h         = (const float*)d_in[0];
    const float* pos       = (const float*)d_in[1];
    const float* edge_sh   = (const float*)d_in[2];
    const float* edge_fts  = (const float*)d_in[3];
    const float* W_node_l  = (const float*)d_in[4];
    const float* W_rad_l   = (const float*)d_in[5];
    const float* W_prod_l  = (const float*)d_in[6];
    const float* ms_W1     = (const float*)d_in[7];
    const float* ms_b1     = (const float*)d_in[8];
    const float* ms_W2     = (const float*)d_in[9];
    const float* ms_b2     = (const float*)d_in[10];
    const float* vg_Wq     = (const float*)d_in[11];
    const float* vg_Wk     = (const float*)d_in[12];
    const float* W_node_h  = (const float*)d_in[13];
    const float* W_rad_h   = (const float*)d_in[14];
    const float* W_prod_h  = (const float*)d_in[15];
    const int*   eidx      = (const int*)d_in[16];
    const int* src = eidx;
    const int* dst = eidx + CE;
    float* out = (float*)d_out;

    static int smem_set = 0;
    if (!smem_set) {
        cudaFuncSetAttribute(fused_gemms, cudaFuncAttributeMaxDynamicSharedMemorySize,
                             FUSED_SMEM);
        smem_set = 1;
    }

    void *p_hW, *p_upd, *p_hlocal, *p_counts, *p_offsets, *p_cursor, *p_eids, *p_m,
         *p_master, *p_rank, *p_adj, *p_arec, *p_hm, *p_posm, *p_q, *p_k, *p_hWh,
         *p_hhier, *p_updtf, *p_wpltf, *p_wphtf, *p_updmtf;
    cudaGetSymbolAddress(&p_hW, g_hW);
    cudaGetSymbolAddress(&p_upd, g_upd);
    cudaGetSymbolAddress(&p_hlocal, g_hlocal);
    cudaGetSymbolAddress(&p_counts, g_counts);
    cudaGetSymbolAddress(&p_offsets, g_offsets);
    cudaGetSymbolAddress(&p_cursor, g_cursor);
    cudaGetSymbolAddress(&p_eids, g_eids);
    cudaGetSymbolAddress(&p_m, g_m);
    cudaGetSymbolAddress(&p_master, g_master);
    cudaGetSymbolAddress(&p_rank, g_rank);
    cudaGetSymbolAddress(&p_adj, g_adj);
    cudaGetSymbolAddress(&p_arec, g_arec);
    cudaGetSymbolAddress(&p_hm, g_hm);
    cudaGetSymbolAddress(&p_posm, g_posm);
    cudaGetSymbolAddress(&p_q, g_q);
    cudaGetSymbolAddress(&p_k, g_k);
    cudaGetSymbolAddress(&p_hWh, g_hWh);
    cudaGetSymbolAddress(&p_hhier, g_hhier);
    cudaGetSymbolAddress(&p_updtf, g_updtf);
    cudaGetSymbolAddress(&p_wpltf, g_wpltf);
    cudaGetSymbolAddress(&p_wphtf, g_wphtf);
    cudaGetSymbolAddress(&p_updmtf, g_updmtf);

    // CSR build
    zero_int_kernel<<<CN / 256, 256>>>((int*)p_counts, CN);
    count_kernel<<<CE / 256, 256>>>(dst, (int*)p_counts);
    scan_kernel<<<1, 1024>>>((int*)p_counts, (int*)p_offsets, (int*)p_cursor);
    scatter_kernel<<<CE / 256, 256>>>(dst, (int*)p_cursor, (int*)p_eids);

    // weight tf32 pre-conversion
    f2tf_kernel<<<(CDOUT * CDOUT / 4 + 255) / 256, 256>>>(W_prod_l, (unsigned*)p_wpltf,
                                                          CDOUT * CDOUT / 4);
    f2tf_kernel<<<(CDOUT * CDOUT / 4 + 255) / 256, 256>>>(W_prod_h, (unsigned*)p_wphtf,
                                                          CDOUT * CDOUT / 4);

    // hW = h @ W_node_l (fp32)
    sgemm128<<<dim3(1, CN / 128), 256>>>(h, CF, W_node_l, CF, (float*)p_hW, CF, CF,
                                         (const float*)0, 0, 0);
    // edge message accumulation (fp32 + fused tf32 output)
    edge_accum_kernel<<<CN, 128>>>((const float*)p_hW, edge_sh, edge_fts, W_rad_l,
                                   src, (const int*)p_offsets, (const int*)p_eids,
                                   (float*)p_upd, (unsigned*)p_updtf);
    // fused: fp32 exact slice (cols 0..127, bit-identical) + tf32 TC (cols 128..1151)
    fused_gemms<<<1152, 256, FUSED_SMEM>>>(
        (const float*)p_upd, W_prod_l, (float*)p_hlocal, h,
        (const unsigned*)p_updtf, (const unsigned*)p_wpltf + CF, (float*)p_hlocal + CF);
    // gating MLP
    mlp_kernel<<<CN / 16, 128>>>((const float*)p_hlocal, ms_W1, ms_b1, ms_W2, ms_b2,
                                 (float*)p_m);
    // exact top-K + fused rank init/set + master-index output
    topk_kernel<<<1, 1024>>>((const float*)p_m, (int*)p_master, (int*)p_rank,
                             out + OFF_MI);
    // induced adjacency
    zero_u8_kernel<<<(CK * CK) / 256, 256>>>((unsigned char*)p_adj, CK * CK);
    adj_kernel<<<CE / 256, 256>>>(src, dst, (const int*)p_rank, (unsigned char*)p_adj);
    // gather masters
    gather_kernel<<<CK, 128>>>((const float*)p_hlocal, pos, (const int*)p_master,
                               (float*)p_hm, (float*)p_posm);
    // q / k projections (exact fp32)
    sgemm64<<<dim3(CDA / 64, CK / 64), 256>>>((const float*)p_hm, CDOUT, vg_Wq, CDA,
                                              (float*)p_q, CDA, CF);
    sgemm64<<<dim3(CDA / 64, CK / 64), 256>>>((const float*)p_hm, CDOUT, vg_Wk, CDA,
                                              (float*)p_k, CDA, CF);
    // attention -> A_virtual (tiled, K through smem)
    attn_kernel<<<CK / 16, 256>>>((const float*)p_q, (const float*)p_k, out + OFF_AV);
    // A_rec mask (tiled transpose, coalesced)
    arec_kernel<<<dim3(CK / 32, CK / 32), 256>>>(out + OFF_AV,
                                                 (const unsigned char*)p_adj,
                                                 (unsigned char*)p_arec);
    // hWh = h_m @ W_node_h (fp32, 32 blocks)
    sgemm64<<<dim3(CF / 64, CK / 64), 256>>>((const float*)p_hm, CDOUT,
                                             W_node_h, CF, (float*)p_hWh, CF, CDOUT);
    // masked geometry accumulation -> upd_m (tf32 bits, 128-wide chunks)
    geom_kernel<<<CK, 128>>>((const float*)p_posm, (const float*)p_hWh,
                             (const unsigned char*)p_arec, W_rad_h,
                             (unsigned*)p_updmtf);
    // h_hier = upd_m @ W_prod_h + h_m (tf32 TC)
    tgemm128<<<dim3(CDOUT / 128, CK / 128), 256>>>(
        (const unsigned*)p_updmtf, CDOUT, (const unsigned*)p_wphtf, CDOUT,
        (float*)p_hhier, CDOUT, CDOUT, (const float*)p_hm, CDOUT);
    // final blend + m output
    blend_kernel<<<CN, 128>>>((const float*)p_hlocal, (const float*)p_hhier,
                              (const float*)p_m, (const int*)p_rank,
                              out, out + OFF_M);
}

// round 17
// speedup vs baseline: 1.2614x; 1.0192x over previous
#include <cuda_runtime.h>
#include <cuda_bf16.h>
#include <math.h>

#define CN 16384
#define CE 131072
#define CF 128
#define CL 9
#define CR 8
#define CDOUT 1152
#define CK 1024
#define CHID 64
#define CDA 64
#define CRCUT 5.0f
#define CEPS 1e-9f
#define FPI 3.14159265358979323846f

#define OFF_AV ((long long)CN * CDOUT)
#define OFF_M  (OFF_AV + (long long)CK * CK)
#define OFF_MI (OFF_M + CN)

// ---------------- device scratch ----------------
__device__ float g_hW[CN * CF];
__device__ float g_upd[CN * CDOUT];
__device__ float g_hlocal[CN * CDOUT];
__device__ int   g_counts[CN];
__device__ int   g_offsets[CN + 1];
__device__ int   g_cursor[CN];
__device__ int   g_eids[CE];
__device__ float g_m[CN];
__device__ int   g_master[CK];
__device__ int   g_rank[CN];
__device__ unsigned char g_adj[CK * CK];
__device__ unsigned char g_arec[CK * CK];
__device__ float g_hm[CK * CDOUT];
__device__ float g_posm[CK * 3];
__device__ float g_q[CK * CDA];
__device__ float g_k[CK * CDA];
__device__ float g_hWh[CK * CF];
__device__ float g_hhier[CK * CDOUT];
__device__ unsigned g_updtf[CN * CDOUT];
__device__ unsigned g_wpltf[CDOUT * CDOUT];
__device__ unsigned g_wphtf[CDOUT * CDOUT];
__device__ unsigned g_updmtf[CK * CDOUT];

// ---------------- utility ----------------
__global__ void zero_int_kernel(int* p, int n) {
    int i = blockIdx.x * blockDim.x + threadIdx.x;
    if (i < n) p[i] = 0;
}
__global__ void zero_u8_kernel(unsigned char* p, int n) {
    int i = blockIdx.x * blockDim.x + threadIdx.x;
    if (i < n) p[i] = 0;
}

__device__ __forceinline__ unsigned f2tf32(float f) {
    unsigned u;
    asm("cvt.rna.tf32.f32 %0, %1;" : "=r"(u) : "f"(f));
    return u;
}

__global__ void f2tf_kernel(const float* __restrict__ in, unsigned* __restrict__ out, int n4) {
    int i = blockIdx.x * blockDim.x + threadIdx.x;
    if (i < n4) {
        float4 v = ((const float4*)in)[i];
        uint4 u = make_uint4(f2tf32(v.x), f2tf32(v.y), f2tf32(v.z), f2tf32(v.w));
        ((uint4*)out)[i] = u;
    }
}

#define CP_ASYNC16(dst_u32, src_ptr) \
    asm volatile("cp.async.cg.shared.global [%0], [%1], 16;" :: "r"(dst_u32), "l"(src_ptr))
#define CP_COMMIT() asm volatile("cp.async.commit_group;" ::: "memory")
#define CP_WAIT1()  asm volatile("cp.async.wait_group 1;" ::: "memory")
#define CP_WAIT0()  asm volatile("cp.async.wait_group 0;" ::: "memory")

// ================= fused big GEMM (unchanged from R16) =================
#define FUSED_SMEM 56832

__global__ __launch_bounds__(256, 2) void fused_gemms(
    const float* __restrict__ Afp, const float* __restrict__ Bfp,
    float* __restrict__ Cfp, const float* __restrict__ addfp,
    const unsigned* __restrict__ Atf, const unsigned* __restrict__ Btf,
    float* __restrict__ Ctf)
{
    extern __shared__ __align__(16) char smem_raw[];
    const int tid = threadIdx.x;

    if (blockIdx.x < 128) {
        typedef float AsT[8][128];
        typedef float BsT[8][128];
        AsT* As = (AsT*)smem_raw;
        BsT* Bs = (BsT*)(smem_raw + 2 * 8 * 128 * 4);
        const int tx = tid & 15, ty = tid >> 4;
        const int m0 = blockIdx.x * 128;
        const int lda = CDOUT, ldb = CDOUT, ldc = CDOUT, ldadd = CF;
        const int Ksize = CDOUT;

        float acc[8][8];
#pragma unroll
        for (int i = 0; i < 8; i++)
#pragma unroll
            for (int j = 0; j < 8; j++) acc[i][j] = 0.f;

        const int arow = tid >> 1;
        const int akc  = (tid & 1) * 4;
        const int brow = tid >> 5;
        const int bcol = (tid & 31) * 4;

        float4 av = *(const float4*)(Afp + (long long)(m0 + arow) * lda + akc);
        float4 bv = *(const float4*)(Bfp + (long long)brow * ldb + bcol);
        As[0][akc + 0][arow] = av.x; As[0][akc + 1][arow] = av.y;
        As[0][akc + 2][arow] = av.z; As[0][akc + 3][arow] = av.w;
        *(float4*)&Bs[0][brow][bcol] = bv;
        __syncthreads();

        const int KT = Ksize >> 3;
        for (int kt = 0; kt < KT; ++kt) {
            int cur = kt & 1;
            if (kt + 1 < KT) {
                int k0 = (kt + 1) << 3;
                av = *(const float4*)(Afp + (long long)(m0 + arow) * lda + k0 + akc);
                bv = *(const float4*)(Bfp + (long long)(k0 + brow) * ldb + bcol);
            }
#pragma unroll
            for (int kk = 0; kk < 8; ++kk) {
                float a[8], b[8];
                *(float4*)a       = *(const float4*)&As[cur][kk][ty * 4];
                *(float4*)(a + 4) = *(const float4*)&As[cur][kk][ty * 4 + 64];
                *(float4*)b       = *(const float4*)&Bs[cur][kk][tx * 4];
                *(float4*)(b + 4) = *(const float4*)&Bs[cur][kk][tx * 4 + 64];
#pragma unroll
                for (int i = 0; i < 8; i++)
#pragma unroll
                    for (int j = 0; j < 8; j++) acc[i][j] += a[i] * b[j];
            }
            if (kt + 1 < KT) {
                int nxt = cur ^ 1;
                As[nxt][akc + 0][arow] = av.x; As[nxt][akc + 1][arow] = av.y;
                As[nxt][akc + 2][arow] = av.z; As[nxt][akc + 3][arow] = av.w;
                *(float4*)&Bs[nxt][brow][bcol] = bv;
            }
            __syncthreads();
        }

#pragma unroll
        for (int i = 0; i < 8; i++) {
            int row = m0 + ty * 4 + (i & 3) + (i >> 2) * 64;
#pragma unroll
            for (int j = 0; j < 8; j++) {
                int col = tx * 4 + (j & 3) + (j >> 2) * 64;
                float v = acc[i][j];
                if (col < CF) v += addfp[(long long)row * ldadd + col];
                Cfp[(long long)row * ldc + col] = v;
            }
        }
    } else {
        typedef unsigned AsTT[128][20];
        typedef unsigned BsTT[16][136];
        AsTT* As = (AsTT*)smem_raw;
        BsTT* Bs = (BsTT*)(smem_raw + 3 * 128 * 20 * 4);
        const int b = blockIdx.x - 128;
        const int lane = tid & 31, wid = tid >> 5;
        const int wm = wid >> 2, wn = wid & 3;
        const int m0 = (b >> 3) * 128, n0 = (b & 7) * 128;
        const int g = lane >> 2, tq = lane & 3;
        const int lda = CDOUT, ldb = CDOUT, ldc = CDOUT;

        float acc[4][4][4];
#pragma unroll
        for (int i = 0; i < 4; i++)
#pragma unroll
            for (int j = 0; j < 4; j++)
#pragma unroll
                for (int c = 0; c < 4; c++) acc[i][j][c] = 0.f;

        const int a_r = tid >> 2, a_c = (tid & 3) * 4;
        const int b_r = tid >> 5, b_c = (tid & 31) * 4;
        const unsigned* Aptr = Atf + (long long)(m0 + a_r) * lda + a_c;
        const unsigned* Bptr = Btf + (long long)b_r * ldb + n0 + b_c;

        unsigned sA0[3], sA1[3], sB0[3], sB1[3];
#pragma unroll
        for (int s = 0; s < 3; s++) {
            sA0[s] = (unsigned)__cvta_generic_to_shared(&As[s][a_r][a_c]);
            sA1[s] = (unsigned)__cvta_generic_to_shared(&As[s][a_r + 64][a_c]);
            sB0[s] = (unsigned)__cvta_generic_to_shared(&Bs[s][b_r][b_c]);
            sB1[s] = (unsigned)__cvta_generic_to_shared(&Bs[s][b_r + 8][b_c]);
        }

        const int KT = CDOUT >> 4;
        {
            CP_ASYNC16(sA0[0], Aptr);
            CP_ASYNC16(sA1[0], Aptr + (long long)64 * lda);
            CP_ASYNC16(sB0[0], Bptr);
            CP_ASYNC16(sB1[0], Bptr + (long long)8 * ldb);
            CP_COMMIT();
            CP_ASYNC16(sA0[1], Aptr + 16);
            CP_ASYNC16(sA1[1], Aptr + 16 + (long long)64 * lda);
            CP_ASYNC16(sB0[1], Bptr + (long long)16 * ldb);
            CP_ASYNC16(sB1[1], Bptr + (long long)24 * ldb);
            CP_COMMIT();
        }

        int cur = 0;
        for (int kt = 0; kt < KT; ++kt) {
            if (kt + 1 < KT) { CP_WAIT1(); } else { CP_WAIT0(); }
            __syncthreads();
            if (kt + 2 < KT) {
                int s = cur + 2; if (s >= 3) s -= 3;
                const unsigned* Ap = Aptr + (kt + 2) * 16;
                const unsigned* Bp = Bptr + (long long)((kt + 2) * 16) * ldb;
                CP_ASYNC16(sA0[s], Ap);
                CP_ASYNC16(sA1[s], Ap + (long long)64 * lda);
                CP_ASYNC16(sB0[s], Bp);
                CP_ASYNC16(sB1[s], Bp + (long long)8 * ldb);
                CP_COMMIT();
            }
#pragma unroll
            for (int kk = 0; kk < 16; kk += 8) {
                unsigned af[4][4];
#pragma unroll
                for (int mi = 0; mi < 4; mi++) {
                    int r = wm * 64 + mi * 16 + g;
                    af[mi][0] = As[cur][r][kk + tq];
                    af[mi][1] = As[cur][r + 8][kk + tq];
                    af[mi][2] = As[cur][r][kk + tq + 4];
                    af[mi][3] = As[cur][r + 8][kk + tq + 4];
                }
                unsigned bf[4][2];
#pragma unroll
                for (int nj = 0; nj < 4; nj++) {
                    int cidx = wn * 32 + nj * 8 + g;
                    bf[nj][0] = Bs[cur][kk + tq][cidx];
                    bf[nj][1] = Bs[cur][kk + tq + 4][cidx];
                }
#pragma unroll
                for (int mi = 0; mi < 4; mi++)
#pragma unroll
                    for (int nj = 0; nj < 4; nj++)
                        asm volatile(
                            "mma.sync.aligned.m16n8k8.row.col.f32.tf32.tf32.f32 "
                            "{%0,%1,%2,%3}, {%4,%5,%6,%7}, {%8,%9}, {%0,%1,%2,%3};"
                            : "+f"(acc[mi][nj][0]), "+f"(acc[mi][nj][1]),
                              "+f"(acc[mi][nj][2]), "+f"(acc[mi][nj][3])
                            : "r"(af[mi][0]), "r"(af[mi][1]), "r"(af[mi][2]), "r"(af[mi][3]),
                              "r"(bf[nj][0]), "r"(bf[nj][1]));
            }
            cur = (cur + 1 == 3) ? 0 : cur + 1;
        }

#pragma unroll
        for (int mi = 0; mi < 4; mi++) {
            int r = wm * 64 + mi * 16 + g;
#pragma unroll
            for (int nj = 0; nj < 4; nj++) {
                int c = wn * 32 + nj * 8 + tq * 2;
                long long i0 = (long long)(m0 + r) * ldc + n0 + c;
                long long i1 = (long long)(m0 + r + 8) * ldc + n0 + c;
                *(float2*)(Ctf + i0) = make_float2(acc[mi][nj][0], acc[mi][nj][1]);
                *(float2*)(Ctf + i1) = make_float2(acc[mi][nj][2], acc[mi][nj][3]);
            }
        }
    }
}

// ---------------- standalone tf32 GEMM (hhier, unchanged) ----------------
__global__ __launch_bounds__(256) void tgemm128(
    const unsigned* __restrict__ A, int lda,
    const unsigned* __restrict__ B, int ldb,
    float* __restrict__ C, int ldc, int Ksize,
    const float* __restrict__ addsrc, int ldadd)
{
    __shared__ __align__(16) unsigned As[3][128][20];
    __shared__ __align__(16) unsigned Bs[3][16][136];
    const int tid = threadIdx.x;
    const int lane = tid & 31, wid = tid >> 5;
    const int wm = wid >> 2, wn = wid & 3;
    const int m0 = blockIdx.y * 128, n0 = blockIdx.x * 128;
    const int g = lane >> 2, tq = lane & 3;

    float acc[4][4][4];
#pragma unroll
    for (int i = 0; i < 4; i++)
#pragma unroll
        for (int j = 0; j < 4; j++)
#pragma unroll
            for (int c = 0; c < 4; c++) acc[i][j][c] = 0.f;

    const int a_r = tid >> 2, a_c = (tid & 3) * 4;
    const int b_r = tid >> 5, b_c = (tid & 31) * 4;
    const unsigned* Aptr = A + (long long)(m0 + a_r) * lda + a_c;
    const unsigned* Bptr = B + (long long)b_r * ldb + n0 + b_c;

    unsigned sA0[3], sA1[3], sB0[3], sB1[3];
#pragma unroll
    for (int s = 0; s < 3; s++) {
        sA0[s] = (unsigned)__cvta_generic_to_shared(&As[s][a_r][a_c]);
        sA1[s] = (unsigned)__cvta_generic_to_shared(&As[s][a_r + 64][a_c]);
        sB0[s] = (unsigned)__cvta_generic_to_shared(&Bs[s][b_r][b_c]);
        sB1[s] = (unsigned)__cvta_generic_to_shared(&Bs[s][b_r + 8][b_c]);
    }

    const int KT = Ksize >> 4;
    {
        CP_ASYNC16(sA0[0], Aptr);
        CP_ASYNC16(sA1[0], Aptr + (long long)64 * lda);
        CP_ASYNC16(sB0[0], Bptr);
        CP_ASYNC16(sB1[0], Bptr + (long long)8 * ldb);
        CP_COMMIT();
        CP_ASYNC16(sA0[1], Aptr + 16);
        CP_ASYNC16(sA1[1], Aptr + 16 + (long long)64 * lda);
        CP_ASYNC16(sB0[1], Bptr + (long long)16 * ldb);
        CP_ASYNC16(sB1[1], Bptr + (long long)24 * ldb);
        CP_COMMIT();
    }

    int cur = 0;
    for (int kt = 0; kt < KT; ++kt) {
        if (kt + 1 < KT) { CP_WAIT1(); } else { CP_WAIT0(); }
        __syncthreads();
        if (kt + 2 < KT) {
            int s = cur + 2; if (s >= 3) s -= 3;
            const unsigned* Ap = Aptr + (kt + 2) * 16;
            const unsigned* Bp = Bptr + (long long)((kt + 2) * 16) * ldb;
            CP_ASYNC16(sA0[s], Ap);
            CP_ASYNC16(sA1[s], Ap + (long long)64 * lda);
            CP_ASYNC16(sB0[s], Bp);
            CP_ASYNC16(sB1[s], Bp + (long long)8 * ldb);
            CP_COMMIT();
        }
#pragma unroll
        for (int kk = 0; kk < 16; kk += 8) {
            unsigned af[4][4];
#pragma unroll
            for (int mi = 0; mi < 4; mi++) {
                int r = wm * 64 + mi * 16 + g;
                af[mi][0] = As[cur][r][kk + tq];
                af[mi][1] = As[cur][r + 8][kk + tq];
                af[mi][2] = As[cur][r][kk + tq + 4];
                af[mi][3] = As[cur][r + 8][kk + tq + 4];
            }
            unsigned bf[4][2];
#pragma unroll
            for (int nj = 0; nj < 4; nj++) {
                int cidx = wn * 32 + nj * 8 + g;
                bf[nj][0] = Bs[cur][kk + tq][cidx];
                bf[nj][1] = Bs[cur][kk + tq + 4][cidx];
            }
#pragma unroll
            for (int mi = 0; mi < 4; mi++)
#pragma unroll
                for (int nj = 0; nj < 4; nj++)
                    asm volatile(
                        "mma.sync.aligned.m16n8k8.row.col.f32.tf32.tf32.f32 "
                        "{%0,%1,%2,%3}, {%4,%5,%6,%7}, {%8,%9}, {%0,%1,%2,%3};"
                        : "+f"(acc[mi][nj][0]), "+f"(acc[mi][nj][1]),
                          "+f"(acc[mi][nj][2]), "+f"(acc[mi][nj][3])
                        : "r"(af[mi][0]), "r"(af[mi][1]), "r"(af[mi][2]), "r"(af[mi][3]),
                          "r"(bf[nj][0]), "r"(bf[nj][1]));
        }
        cur = (cur + 1 == 3) ? 0 : cur + 1;
    }

#pragma unroll
    for (int mi = 0; mi < 4; mi++) {
        int r = wm * 64 + mi * 16 + g;
#pragma unroll
        for (int nj = 0; nj < 4; nj++) {
            int c = wn * 32 + nj * 8 + tq * 2;
            long long i0 = (long long)(m0 + r) * ldc + n0 + c;
            long long i1 = (long long)(m0 + r + 8) * ldc + n0 + c;
            float2 v0 = make_float2(acc[mi][nj][0], acc[mi][nj][1]);
            float2 v1 = make_float2(acc[mi][nj][2], acc[mi][nj][3]);
            if (addsrc) {
                long long a0 = (long long)(m0 + r) * ldadd + n0 + c;
                long long a1 = (long long)(m0 + r + 8) * ldadd + n0 + c;
                v0.x += addsrc[a0]; v0.y += addsrc[a0 + 1];
                v1.x += addsrc[a1]; v1.y += addsrc[a1 + 1];
            }
            *(float2*)(C + i0) = v0;
            *(float2*)(C + i1) = v1;
        }
    }
}

// ---------------- SGEMM 128x128 fp32 (hW) ----------------
__global__ __launch_bounds__(256) void sgemm128(
    const float* __restrict__ A, int lda,
    const float* __restrict__ B, int ldb,
    float* __restrict__ C, int ldc, int Ksize,
    const float* __restrict__ addsrc, int ldadd, int addcols)
{
    __shared__ float As[2][8][128];
    __shared__ float Bs[2][8][128];
    const int tid = threadIdx.x;
    const int tx = tid & 15, ty = tid >> 4;
    const int m0 = blockIdx.y * 128;
    const int n0 = blockIdx.x * 128;

    float acc[8][8];
#pragma unroll
    for (int i = 0; i < 8; i++)
#pragma unroll
        for (int j = 0; j < 8; j++) acc[i][j] = 0.f;

    const int arow = tid >> 1;
    const int akc  = (tid & 1) * 4;
    const int brow = tid >> 5;
    const int bcol = (tid & 31) * 4;

    float4 av = *(const float4*)(A + (long long)(m0 + arow) * lda + akc);
    float4 bv = *(const float4*)(B + (long long)brow * ldb + n0 + bcol);
    As[0][akc + 0][arow] = av.x; As[0][akc + 1][arow] = av.y;
    As[0][akc + 2][arow] = av.z; As[0][akc + 3][arow] = av.w;
    *(float4*)&Bs[0][brow][bcol] = bv;
    __syncthreads();

    const int KT = Ksize >> 3;
    for (int kt = 0; kt < KT; ++kt) {
        int cur = kt & 1;
        if (kt + 1 < KT) {
            int k0 = (kt + 1) << 3;
            av = *(const float4*)(A + (long long)(m0 + arow) * lda + k0 + akc);
            bv = *(const float4*)(B + (long long)(k0 + brow) * ldb + n0 + bcol);
        }
#pragma unroll
        for (int kk = 0; kk < 8; ++kk) {
            float a[8], b[8];
            *(float4*)a       = *(const float4*)&As[cur][kk][ty * 4];
            *(float4*)(a + 4) = *(const float4*)&As[cur][kk][ty * 4 + 64];
            *(float4*)b       = *(const float4*)&Bs[cur][kk][tx * 4];
            *(float4*)(b + 4) = *(const float4*)&Bs[cur][kk][tx * 4 + 64];
#pragma unroll
            for (int i = 0; i < 8; i++)
#pragma unroll
                for (int j = 0; j < 8; j++) acc[i][j] += a[i] * b[j];
        }
        if (kt + 1 < KT) {
            int nxt = cur ^ 1;
            As[nxt][akc + 0][arow] = av.x; As[nxt][akc + 1][arow] = av.y;
            As[nxt][akc + 2][arow] = av.z; As[nxt][akc + 3][arow] = av.w;
            *(float4*)&Bs[nxt][brow][bcol] = bv;
        }
        __syncthreads();
    }

#pragma unroll
    for (int i = 0; i < 8; i++) {
        int row = m0 + ty * 4 + (i & 3) + (i >> 2) * 64;
#pragma unroll
        for (int j = 0; j < 8; j++) {
            int col = n0 + tx * 4 + (j & 3) + (j >> 2) * 64;
            float v = acc[i][j];
            if (col < addcols) v += addsrc[(long long)row * ldadd + col];
            C[(long long)row * ldc + col] = v;
        }
    }
}

// ---------------- 64x64 fp32 tile body (shared by q/k/hWh dispatcher) ----------------
__device__ __forceinline__ void sg64_body(
    const float* __restrict__ A, int lda,
    const float* __restrict__ B, int ldb,
    float* __restrict__ C, int ldc, int Ksize, int m0, int n0,
    float (*As)[64], float (*Bs)[64])
{
    const int tid = threadIdx.x;
    const int tx = tid & 15, ty = tid >> 4;
    float acc[4][4];
#pragma unroll
    for (int i = 0; i < 4; i++)
#pragma unroll
        for (int j = 0; j < 4; j++) acc[i][j] = 0.f;

    const int arow = tid >> 2, akc = (tid & 3) * 4;
    const int brow = tid >> 4, bcol = (tid & 15) * 4;
    const int KT = Ksize >> 4;
    for (int kt = 0; kt < KT; ++kt) {
        int k0 = kt << 4;
        float4 av = *(const float4*)(A + (long long)(m0 + arow) * lda + k0 + akc);
        float4 bv = *(const float4*)(B + (long long)(k0 + brow) * ldb + n0 + bcol);
        __syncthreads();
        As[akc + 0][arow] = av.x; As[akc + 1][arow] = av.y;
        As[akc + 2][arow] = av.z; As[akc + 3][arow] = av.w;
        *(float4*)&Bs[brow][bcol] = bv;
        __syncthreads();
#pragma unroll
        for (int kk = 0; kk < 16; ++kk) {
            float4 a4 = *(const float4*)&As[kk][ty * 4];
            float4 b4 = *(const float4*)&Bs[kk][tx * 4];
            float a[4] = {a4.x, a4.y, a4.z, a4.w};
            float b[4] = {b4.x, b4.y, b4.z, b4.w};
#pragma unroll
            for (int i = 0; i < 4; i++)
#pragma unroll
                for (int j = 0; j < 4; j++) acc[i][j] += a[i] * b[j];
        }
    }
#pragma unroll
    for (int i = 0; i < 4; i++) {
        int row = m0 + ty * 4 + i;
#pragma unroll
        for (int j = 0; j < 4; j++)
            C[(long long)row * ldc + n0 + tx * 4 + j] = acc[i][j];
    }
}

// one launch for q (blocks 0..15), k (16..31), hWh (32..63); bodies identical to
// the previous separate sgemm64 launches -> bit-identical outputs.
__global__ __launch_bounds__(256) void qkh_kernel(
    const float* __restrict__ hm,
    const float* __restrict__ Wq, const float* __restrict__ Wk,
    const float* __restrict__ Wnh,
    float* __restrict__ q, float* __restrict__ k, float* __restrict__ hWh)
{
    __shared__ float As[16][64];
    __shared__ float Bs[16][64];
    const int b = blockIdx.x;
    if (b < 16) {
        sg64_body(hm, CDOUT, Wq, CDA, q, CDA, CF, b * 64, 0, As, Bs);
    } else if (b < 32) {
        sg64_body(hm, CDOUT, Wk, CDA, k, CDA, CF, (b - 16) * 64, 0, As, Bs);
    } else {
        int i = b - 32;
        sg64_body(hm, CDOUT, Wnh, CF, hWh, CF, CDOUT, (i >> 1) * 64, (i & 1) * 64, As, Bs);
    }
}

// ---------------- CSR build ----------------
__global__ void count_kernel(const int* __restrict__ dstArr, int* __restrict__ counts) {
    int e = blockIdx.x * blockDim.x + threadIdx.x;
    if (e < CE) atomicAdd(&counts[dstArr[e]], 1);
}
__global__ __launch_bounds__(1024) void scan_kernel(
    const int* __restrict__ counts, int* __restrict__ offsets, int* __restrict__ cursor)
{
    __shared__ int s[1024];
    int tid = threadIdx.x;
    int base = tid * 16;
    int loc[16]; int sum = 0;
#pragma unroll
    for (int i = 0; i < 16; i++) { loc[i] = sum; sum += counts[base + i]; }
    s[tid] = sum; __syncthreads();
    for (int off = 1; off < 1024; off <<= 1) {
        int x = (tid >= off) ? s[tid - off] : 0;
        __syncthreads();
        s[tid] += x;
        __syncthreads();
    }
    int excl = s[tid] - sum;
#pragma unroll
    for (int i = 0; i < 16; i++) { int o = excl + loc[i]; offsets[base + i] = o; cursor[base + i] = o; }
    if (tid == 1023) offsets[CN] = excl + sum;
}
__global__ void scatter_kernel(const int* __restrict__ dstArr, int* __restrict__ cursor,
                               int* __restrict__ eids) {
    int e = blockIdx.x * blockDim.x + threadIdx.x;
    if (e < CE) { int p = atomicAdd(&cursor[dstArr[e]], 1); eids[p] = e; }
}

// ---------------- edge accumulation: 4 nodes/block, fused tf32 output ----------------
__global__ __launch_bounds__(128) void edge_accum_kernel(
    const float* __restrict__ hW, const float* __restrict__ edge_sh,
    const float* __restrict__ edge_feats, const float* __restrict__ W_rad_l,
    const int* __restrict__ srcArr, const int* __restrict__ offsets,
    const int* __restrict__ eids, float* __restrict__ upd,
    unsigned* __restrict__ updtf)
{
    __shared__ float Wrl[CR][CF];
    __shared__ int list[1024];
    const int tid = threadIdx.x;
#pragma unroll
    for (int r = 0; r < CR; ++r) Wrl[r][tid] = W_rad_l[r * CF + tid];

#pragma unroll 1
    for (int s = 0; s < 4; ++s) {
        const int n = blockIdx.x * 4 + s;
        __syncthreads();   // Wrl ready (first iter) / list reuse (later iters)
        const int s0 = offsets[n], s1 = offsets[n + 1];
        const int deg = s1 - s0;
        const int use = (deg <= 1024) ? deg : 0;
        for (int i = tid; i < use; i += 128) list[i] = eids[s0 + i];
        __syncthreads();
        if (tid == 0 && use > 1) {
            for (int a = 1; a < use; a++) {
                int v = list[a]; int b = a - 1;
                while (b >= 0 && list[b] > v) { list[b + 1] = list[b]; b--; }
                list[b + 1] = v;
            }
        }
        __syncthreads();
        float acc[CL];
#pragma unroll
        for (int l = 0; l < CL; l++) acc[l] = 0.f;
        for (int q = 0; q < deg; ++q) {
            int e = (deg <= 1024) ? list[q] : eids[s0 + q];
            const float4* ef4 = (const float4*)(edge_feats + (long long)e * CR);
            float4 e0 = __ldg(&ef4[0]);
            float4 e1 = __ldg(&ef4[1]);
            float rs = e0.x * Wrl[0][tid] + e0.y * Wrl[1][tid] + e0.z * Wrl[2][tid] + e0.w * Wrl[3][tid]
                     + e1.x * Wrl[4][tid] + e1.y * Wrl[5][tid] + e1.z * Wrl[6][tid] + e1.w * Wrl[7][tid];
            int sidx = __ldg(&srcArr[e]);
            float t = __ldg(&hW[(long long)sidx * CF + tid]) * rs;
#pragma unroll
            for (int l = 0; l < CL; l++) acc[l] += __ldg(&edge_sh[(long long)e * CL + l]) * t;
        }
        long long obase = (long long)n * CDOUT + tid;
#pragma unroll
        for (int l = 0; l < CL; l++) {
            upd[obase + l * CF] = acc[l];
            updtf[obase + l * CF] = f2tf32(acc[l]);
        }
    }
}

// ---------------- gating MLP ----------------
__global__ __launch_bounds__(128) void mlp_kernel(
    const float* __restrict__ hlocal,
    const float* __restrict__ W1, const float* __restrict__ b1,
    const float* __restrict__ W2, const float* __restrict__ b2,
    float* __restrict__ mout)
{
    __shared__ float W1s[CF][CHID];
    __shared__ float hs[16][CF];
    __shared__ float hid[16][CHID];
    const int tid = threadIdx.x;
    const int n0 = blockIdx.x * 16;
    for (int i = tid; i < CF * CHID; i += 128) W1s[i / CHID][i % CHID] = W1[i];
#pragma unroll
    for (int rr = 0; rr < 16; ++rr) hs[rr][tid] = hlocal[(long long)(n0 + rr) * CDOUT + tid];
    __syncthreads();
    for (int idx = tid; idx < 16 * CHID; idx += 128) {
        int rr = idx >> 6, j = idx & 63;
        float a = b1[j];
#pragma unroll 8
        for (int k2 = 0; k2 < CF; k2++) a += hs[rr][k2] * W1s[k2][j];
        hid[rr][j] = a > 0.f ? a : 0.f;
    }
    __syncthreads();
    int rr = tid >> 3, part = tid & 7;
    float sacc = 0.f;
    for (int j = part; j < CHID; j += 8) sacc += hid[rr][j] * W2[j];
    for (int o = 4; o > 0; o >>= 1) sacc += __shfl_down_sync(0xffffffffu, sacc, o, 8);
    if (part == 0) {
        float x = sacc + b2[0];
        mout[n0 + rr] = 1.f / (1.f + expf(-x));
    }
}

// ---------------- exact top-K + rank/outMi fused ----------------
__device__ __forceinline__ unsigned mapf(float f) {
    unsigned u = __float_as_uint(f);
    return (u & 0x80000000u) ? ~u : (u | 0x80000000u);
}
__global__ __launch_bounds__(1024) void topk_kernel(const float* __restrict__ m,
                                                    int* __restrict__ master,
                                                    int* __restrict__ rank,
                                                    float* __restrict__ outMi)
{
    __shared__ unsigned hist[256];
    __shared__ unsigned sPref; __shared__ int sWant;
    __shared__ int wsum[32], woff[32];
    __shared__ int s_eqRun, s_chRun;
    const int tid = threadIdx.x;
    const int lane = tid & 31, wi = tid >> 5;
    unsigned prefix = 0; int want = CK;
    for (int shift = 24; shift >= 0; shift -= 8) {
        if (tid < 256) hist[tid] = 0u;
        __syncthreads();
        for (int i = tid; i < CN; i += 1024) {
            unsigned key = mapf(m[i]);
            if (shift == 24 || (key >> (shift + 8)) == prefix)
                atomicAdd(&hist[(key >> shift) & 255], 1u);
        }
        __syncthreads();
        if (tid == 0) {
            int w = want; int b = 255;
            for (int d = 255; d >= 0; d--) {
                if ((int)hist[d] >= w) { b = d; break; }
                w -= (int)hist[d];
            }
            sPref = (prefix << 8) | (unsigned)b; sWant = w;
        }
        __syncthreads();
        prefix = sPref; want = sWant;
        __syncthreads();
    }
    const unsigned T = prefix; const int needEq = want;
    if (tid == 0) { s_eqRun = 0; s_chRun = 0; }
    __syncthreads();
    for (int base = 0; base < CN; base += 1024) {
        int i = base + tid;
        unsigned key = mapf(m[i]);
        int isG = key > T;
        int isE = key == T;
        unsigned em = __ballot_sync(0xffffffffu, isE);
        if (lane == 0) wsum[wi] = __popc(em);
        __syncthreads();
        if (wi == 0) {
            int v = wsum[lane];
#pragma unroll
            for (int o = 1; o < 32; o <<= 1) {
                int t = __shfl_up_sync(0xffffffffu, v, o);
                if (lane >= o) v += t;
            }
            woff[lane] = v;
        }
        __syncthreads();
        int eqRank = s_eqRun + (wi ? woff[wi - 1] : 0) + __popc(em & ((1u << lane) - 1u));
        int chunkEq = woff[31];
        int chosen = isG || (isE && eqRank < needEq);
        unsigned cm = __ballot_sync(0xffffffffu, chosen);
        if (lane == 0) wsum[wi] = __popc(cm);
        __syncthreads();
        if (wi == 0) {
            int v = wsum[lane];
#pragma unroll
            for (int o = 1; o < 32; o <<= 1) {
                int t = __shfl_up_sync(0xffffffffu, v, o);
                if (lane >= o) v += t;
            }
            woff[lane] = v;
        }
        __syncthreads();
        int pos = s_chRun + (wi ? woff[wi - 1] : 0) + __popc(cm & ((1u << lane) - 1u));
        int chunkCh = woff[31];
        if (chosen && pos < CK) master[pos] = i;
        __syncthreads();
        if (tid == 0) { s_eqRun += chunkEq; s_chRun += chunkCh; }
        __syncthreads();
    }
    for (int i = tid; i < CN; i += 1024) rank[i] = CK;
    __syncthreads();
    if (tid < CK) {
        int n = master[tid];
        rank[n] = tid;
        outMi[tid] = (float)n;
    }
}

__global__ void adj_kernel(const int* __restrict__ src, const int* __restrict__ dst,
                           const int* __restrict__ rank, unsigned char* __restrict__ adj) {
    int e = blockIdx.x * blockDim.x + threadIdx.x;
    if (e < CE) {
        int rs = rank[src[e]], rd = rank[dst[e]];
        if (rs < CK && rd < CK) adj[(long long)rs * CK + rd] = 1;
    }
}

__global__ __launch_bounds__(128) void gather_kernel(
    const float* __restrict__ hlocal, const float* __restrict__ pos,
    const int* __restrict__ master, float* __restrict__ hm, float* __restrict__ posm)
{
    int i = blockIdx.x, tid = threadIdx.x;
    int n = master[i];
#pragma unroll
    for (int l = 0; l < CL; l++)
        hm[(long long)i * CDOUT + l * CF + tid] = hlocal[(long long)n * CDOUT + l * CF + tid];
    if (tid < 3) posm[i * 3 + tid] = pos[n * 3 + tid];
}

// ---------------- attention (tiled K, unchanged) ----------------
__global__ __launch_bounds__(256) void attn_kernel(const float* __restrict__ q,
                                                   const float* __restrict__ k,
                                                   float* __restrict__ AV) {
    __shared__ float qs[16][CDA + 1];
    __shared__ float ks[128][CDA + 1];
    const int i0 = blockIdx.x * 16;
    const int tid = threadIdx.x;
    for (int idx = tid; idx < 16 * CDA; idx += 256)
        qs[idx >> 6][idx & 63] = q[(long long)(i0 + (idx >> 6)) * CDA + (idx & 63)];
    const int il = tid >> 4;
    const int jo = tid & 15;
    for (int jt = 0; jt < CK; jt += 128) {
        __syncthreads();
        for (int idx = tid; idx < 128 * CDA; idx += 256) {
            int r = idx >> 6, c = idx & 63;
            ks[r][c] = k[(long long)(jt + r) * CDA + c];
        }
        __syncthreads();
#pragma unroll 1
        for (int jj = 0; jj < 8; jj++) {
            int j = jo + jj * 16;
            float d = 0.f;
#pragma unroll
            for (int c = 0; c < CDA; c++) d += qs[il][c] * ks[j][c];
            float a = 1.f / (1.f + expf(-d * 0.125f));
            AV[(long long)(i0 + il) * CK + jt + j] = (a > 0.5f) ? a : 0.f;
        }
    }
}

// ---------------- A_rec mask (tiled transpose, unchanged) ----------------
__global__ __launch_bounds__(256) void arec_kernel(
    const float* __restrict__ AV, const unsigned char* __restrict__ adj,
    unsigned char* __restrict__ arec)
{
    __shared__ float avT[32][33];
    __shared__ unsigned char adT[32][33];
    const int bi = blockIdx.y, bj = blockIdx.x;
    const int tx = threadIdx.x & 31, ty = threadIdx.x >> 5;
    for (int r = ty; r < 32; r += 8) {
        avT[r][tx] = AV[(long long)(bj * 32 + r) * CK + bi * 32 + tx];
        adT[r][tx] = adj[(long long)(bj * 32 + r) * CK + bi * 32 + tx];
    }
    __syncthreads();
    for (int r = ty; r < 32; r += 8) {
        int i = bi * 32 + r, j = bj * 32 + tx;
        unsigned char v = 0;
        if (i != j) {
            if (adT[tx][r]) v = 1;
            else if (avT[tx][r] > 0.f || AV[(long long)i * CK + j] > 0.f) v = 1;
        }
        arec[(long long)i * CK + j] = v;
    }
}

// ---------------- geometry accumulation (128-wide chunks, unchanged) ----------------
__global__ __launch_bounds__(128) void geom_kernel(
    const float* __restrict__ posm, const float* __restrict__ hWh,
    const unsigned char* __restrict__ arec, const float* __restrict__ Wrh_g,
    unsigned* __restrict__ updmtf)
{
    __shared__ float Wrh[CR][CF];
    __shared__ float shv[128][CL];
    __shared__ float radv[128][CR];
    __shared__ unsigned char act[128];
    const int i = blockIdx.x, tid = threadIdx.x;
#pragma unroll
    for (int r = 0; r < CR; r++) Wrh[r][tid] = Wrh_g[r * CF + tid];
    const float px = posm[i * 3], py = posm[i * 3 + 1], pz = posm[i * 3 + 2];
    float acc[CL];
#pragma unroll
    for (int l = 0; l < CL; l++) acc[l] = 0.f;

    for (int j0 = 0; j0 < CK; j0 += 128) {
        __syncthreads();
        {
            int j = j0 + tid;
            int a = arec[(long long)i * CK + j];
            act[tid] = (unsigned char)a;
            if (a) {
                float vx = posm[j * 3] - px, vy = posm[j * 3 + 1] - py, vz = posm[j * 3 + 2] - pz;
                float rr = sqrtf(vx * vx + vy * vy + vz * vz);
                float inv = 1.f / fmaxf(rr, CEPS);
                float x = vx * inv, y = vy * inv, z = vz * inv;
                shv[tid][0] = 1.f; shv[tid][1] = x; shv[tid][2] = y; shv[tid][3] = z;
                shv[tid][4] = x * y; shv[tid][5] = y * z; shv[tid][6] = 3.f * z * z - 1.f;
                shv[tid][7] = x * z; shv[tid][8] = x * x - y * y;
                float c = sqrtf(2.f / CRCUT);
                float invr = 1.f / fmaxf(rr, CEPS);
#pragma unroll
                for (int n2 = 1; n2 <= CR; n2++)
                    radv[tid][n2 - 1] = c * sinf((float)n2 * FPI * rr / CRCUT) * invr;
            }
        }
        __syncthreads();
#pragma unroll 1
        for (int jj = 0; jj < 128; jj++) {
            if (!act[jj]) continue;
            int j = j0 + jj;
            float rw = 0.f;
#pragma unroll
            for (int r = 0; r < CR; r++) rw += radv[jj][r] * Wrh[r][tid];
            float t = hWh[(long long)j * CF + tid] * rw;
#pragma unroll
            for (int l = 0; l < CL; l++) acc[l] += shv[jj][l] * t;
        }
    }
    long long ob = (long long)i * CDOUT + tid;
#pragma unroll
    for (int l = 0; l < CL; l++) updmtf[ob + l * CF] = f2tf32(acc[l]);
}

__global__ __launch_bounds__(128) void blend_kernel(
    const float* __restrict__ hlocal, const float* __restrict__ hhier,
    const float* __restrict__ m, const int* __restrict__ rank,
    float* __restrict__ out, float* __restrict__ outm)
{
    int n = blockIdx.x, tid = threadIdx.x;
    float mv = m[n]; int rk = rank[n];
    long long b = (long long)n * CDOUT + tid;
#pragma unroll
    for (int l = 0; l < CL; l++) {
        float hl = hlocal[b + l * CF];
        float he = (rk < CK) ? hhier[(long long)rk * CDOUT + l * CF + tid] : 0.f;
        out[b + l * CF] = (1.f - mv) * hl + mv * he;
    }
    if (tid == 0) outm[n] = mv;
}

// ---------------- launch ----------------
extern "C" void kernel_launch(void* const* d_in, const int* in_sizes, int n_in,
                              void* d_out, int out_size) {
    const float* h         = (const float*)d_in[0];
    const float* pos       = (const float*)d_in[1];
    const float* edge_sh   = (const float*)d_in[2];
    const float* edge_fts  = (const float*)d_in[3];
    const float* W_node_l  = (const float*)d_in[4];
    const float* W_rad_l   = (const float*)d_in[5];
    const float* W_prod_l  = (const float*)d_in[6];
    const float* ms_W1     = (const float*)d_in[7];
    const float* ms_b1     = (const float*)d_in[8];
    const float* ms_W2     = (const float*)d_in[9];
    const float* ms_b2     = (const float*)d_in[10];
    const float* vg_Wq     = (const float*)d_in[11];
    const float* vg_Wk     = (const float*)d_in[12];
    const float* W_node_h  = (const float*)d_in[13];
    const float* W_rad_h   = (const float*)d_in[14];
    const float* W_prod_h  = (const float*)d_in[15];
    const int*   eidx      = (const int*)d_in[16];
    const int* src = eidx;
    const int* dst = eidx + CE;
    float* out = (float*)d_out;

    static int smem_set = 0;
    if (!smem_set) {
        cudaFuncSetAttribute(fused_gemms, cudaFuncAttributeMaxDynamicSharedMemorySize,
                             FUSED_SMEM);
        smem_set = 1;
    }

    void *p_hW, *p_upd, *p_hlocal, *p_counts, *p_offsets, *p_cursor, *p_eids, *p_m,
         *p_master, *p_rank, *p_adj, *p_arec, *p_hm, *p_posm, *p_q, *p_k, *p_hWh,
         *p_hhier, *p_updtf, *p_wpltf, *p_wphtf, *p_updmtf;
    cudaGetSymbolAddress(&p_hW, g_hW);
    cudaGetSymbolAddress(&p_upd, g_upd);
    cudaGetSymbolAddress(&p_hlocal, g_hlocal);
    cudaGetSymbolAddress(&p_counts, g_counts);
    cudaGetSymbolAddress(&p_offsets, g_offsets);
    cudaGetSymbolAddress(&p_cursor, g_cursor);
    cudaGetSymbolAddress(&p_eids, g_eids);
    cudaGetSymbolAddress(&p_m, g_m);
    cudaGetSymbolAddress(&p_master, g_master);
    cudaGetSymbolAddress(&p_rank, g_rank);
    cudaGetSymbolAddress(&p_adj, g_adj);
    cudaGetSymbolAddress(&p_arec, g_arec);
    cudaGetSymbolAddress(&p_hm, g_hm);
    cudaGetSymbolAddress(&p_posm, g_posm);
    cudaGetSymbolAddress(&p_q, g_q);
    cudaGetSymbolAddress(&p_k, g_k);
    cudaGetSymbolAddress(&p_hWh, g_hWh);
    cudaGetSymbolAddress(&p_hhier, g_hhier);
    cudaGetSymbolAddress(&p_updtf, g_updtf);
    cudaGetSymbolAddress(&p_wpltf, g_wpltf);
    cudaGetSymbolAddress(&p_wphtf, g_wphtf);
    cudaGetSymbolAddress(&p_updmtf, g_updmtf);

    // CSR build
    zero_int_kernel<<<CN / 256, 256>>>((int*)p_counts, CN);
    count_kernel<<<CE / 256, 256>>>(dst, (int*)p_counts);
    scan_kernel<<<1, 1024>>>((int*)p_counts, (int*)p_offsets, (int*)p_cursor);
    scatter_kernel<<<CE / 256, 256>>>(dst, (int*)p_cursor, (int*)p_eids);

    // weight tf32 pre-conversion
    f2tf_kernel<<<(CDOUT * CDOUT / 4 + 255) / 256, 256>>>(W_prod_l, (unsigned*)p_wpltf,
                                                          CDOUT * CDOUT / 4);
    f2tf_kernel<<<(CDOUT * CDOUT / 4 + 255) / 256, 256>>>(W_prod_h, (unsigned*)p_wphtf,
                                                          CDOUT * CDOUT / 4);

    // hW = h @ W_node_l (fp32)
    sgemm128<<<dim3(1, CN / 128), 256>>>(h, CF, W_node_l, CF, (float*)p_hW, CF, CF,
                                         (const float*)0, 0, 0);
    // edge message accumulation (4 nodes/block, fused tf32 output)
    edge_accum_kernel<<<CN / 4, 128>>>((const float*)p_hW, edge_sh, edge_fts, W_rad_l,
                                       src, (const int*)p_offsets, (const int*)p_eids,
                                       (float*)p_upd, (unsigned*)p_updtf);
    // fused: fp32 exact slice (cols 0..127, bit-identical) + tf32 TC (cols 128..1151)
    fused_gemms<<<1152, 256, FUSED_SMEM>>>(
        (const float*)p_upd, W_prod_l, (float*)p_hlocal, h,
        (const unsigned*)p_updtf, (const unsigned*)p_wpltf + CF, (float*)p_hlocal + CF);
    // gating MLP
    mlp_kernel<<<CN / 16, 128>>>((const float*)p_hlocal, ms_W1, ms_b1, ms_W2, ms_b2,
                                 (float*)p_m);
    // exact top-K + fused rank init/set + master-index output
    topk_kernel<<<1, 1024>>>((const float*)p_m, (int*)p_master, (int*)p_rank,
                             out + OFF_MI);
    // induced adjacency
    zero_u8_kernel<<<(CK * CK) / 256, 256>>>((unsigned char*)p_adj, CK * CK);
    adj_kernel<<<CE / 256, 256>>>(src, dst, (const int*)p_rank, (unsigned char*)p_adj);
    // gather masters
    gather_kernel<<<CK, 128>>>((const float*)p_hlocal, pos, (const int*)p_master,
                               (float*)p_hm, (float*)p_posm);
    // q / k / hWh in ONE launch (64 blocks; bodies identical to prior sgemm64 calls)
    qkh_kernel<<<64, 256>>>((const float*)p_hm, vg_Wq, vg_Wk, W_node_h,
                            (float*)p_q, (float*)p_k, (float*)p_hWh);
    // attention -> A_virtual (tiled, K through smem)
    attn_kernel<<<CK / 16, 256>>>((const float*)p_q, (const float*)p_k, out + OFF_AV);
    // A_rec mask (tiled transpose, coalesced)
    arec_kernel<<<dim3(CK / 32, CK / 32), 256>>>(out + OFF_AV,
                                                 (const unsigned char*)p_adj,
                                                 (unsigned char*)p_arec);
    // masked geometry accumulation -> upd_m (tf32 bits, 128-wide chunks)
    geom_kernel<<<CK, 128>>>((const float*)p_posm, (const float*)p_hWh,
                             (const unsigned char*)p_arec, W_rad_h,
                             (unsigned*)p_updmtf);
    // h_hier = upd_m @ W_prod_h + h_m (tf32 TC)
    tgemm128<<<dim3(CDOUT / 128, CK / 128), 256>>>(
        (const unsigned*)p_updmtf, CDOUT, (const unsigned*)p_wphtf, CDOUT,
        (float*)p_hhier, CDOUT, CDOUT, (const float*)p_hm, CDOUT);
    // final blend + m output
    blend_kernel<<<CN, 128>>>((const float*)p_hlocal, (const float*)p_hhier,
                              (const float*)p_m, (const int*)p_rank,
                              out, out + OFF_M);
}